// round 9
// baseline (speedup 1.0000x reference)
#include <cuda_runtime.h>
#include <cuda_bf16.h>
#include <cstdint>
#include <cstddef>

// Problem constants
#define NB   16
#define CIN  2048
#define MID  512
#define HW   1024
#define DQK  128
#define NHEAD 4
#define ATT_SCALE 0.08838834764831845f
#define BN_EPS 1e-5f

// GEMM tile: block 128(pos) x 128(ch), K-chunk 64, 8 warps of 32(pos)x64(ch)
#define LDA_P 136                       // A smem row pad
#define A_ST  (64 * LDA_P)              // 8704 floats per A stage (64 k-rows)
#define B_ST  8192                      // packed B floats per K-64 stage (2x4096)
#define GEMM_SMEM ((3 * A_ST + 3 * B_ST) * 4)   // 202752 B

// Flash tile config: x-tile 128, 512 threads (16 warps of 32x32)
#define LDB  136
#define BSZ (32 * LDB)
#define FLDQ 132
#define F_S  (128 * FLDQ)
#define F_B  (2 * F_S)
#define F_M  (F_B + 3 * BSZ)
#define F_L  (F_M + 128)
#define F_SC (F_L + 128)
#define FLASH_SMEM ((F_SC + 128) * 4)  // 188928 B

// Scratch (device globals — allocation-free kernel_launch)
__device__ float g_x   [(size_t)NB * CIN * HW];   // tf32-rounded x [n][ch][pos]
__device__ float g_out1[(size_t)NB * MID * HW];   // [n][ch][pos], tf32
__device__ float g_qk  [(size_t)NB * 1024 * HW];  // q'[d][x] then k'[d][y], tf32
__device__ float g_vT  [(size_t)NB * HW * MID];   // v [n][y][ch], tf32
__device__ float g_attn[(size_t)NB * MID * HW];   // [n][ch][pos], tf32
__device__ float g_w1  [(size_t)MID * CIN];       // B-fragment-packed
__device__ float g_wqkv[(size_t)1536 * MID];      // B-fragment-packed
__device__ float g_w3  [(size_t)CIN * MID];       // B-fragment-packed

// ---------------------------------------------------------------------------
__device__ __forceinline__ float f2tf(float f) {
    uint32_t u;
    asm("cvt.rna.tf32.f32 %0, %1;" : "=r"(u) : "f"(f));
    return __uint_as_float(u);
}

__device__ __forceinline__ void cp16(float* dst, const float* src) {
    uint32_t d = (uint32_t)__cvta_generic_to_shared(dst);
    asm volatile("cp.async.cg.shared.global [%0], [%1], 16;\n" :: "r"(d), "l"(src));
}
#define CP_COMMIT asm volatile("cp.async.commit_group;\n" ::: "memory")
#define CP_WAIT0  asm volatile("cp.async.wait_group 0;\n" ::: "memory")
#define CP_WAIT1  asm volatile("cp.async.wait_group 1;\n" ::: "memory")

// ---------------------------------------------------------------------------
// elementwise tf32 round (x)
// ---------------------------------------------------------------------------
__global__ __launch_bounds__(256) void k_round(const float4* __restrict__ src,
                                               float4* __restrict__ dst, int n4) {
    int i = blockIdx.x * blockDim.x + threadIdx.x;
    if (i < n4) {
        float4 v = src[i];
        dst[i] = make_float4(f2tf(v.x), f2tf(v.y), f2tf(v.z), f2tf(v.w));
    }
}

// ---------------------------------------------------------------------------
// Weight repack into B-fragment order (identical layout to round 7).
//   e = tile*(K*128) + c32*4096 + h*2048 + (ks*4+np)*128 + lane*4 + comp
// ---------------------------------------------------------------------------
__global__ __launch_bounds__(256) void k_repack(const float* __restrict__ src,
                                                float* __restrict__ dst,
                                                int Mout, int K) {
    int e = blockIdx.x * 256 + threadIdx.x;
    if (e >= Mout * K) return;
    int nchunks = K >> 5;
    int comp = e & 3;
    int lane = (e >> 2) & 31;
    int t = e >> 7;
    int np = t & 3, ks = (t >> 2) & 3, h = (t >> 4) & 1;
    int rest = t >> 5;
    int c = rest % nchunks, tile = rest / nchunks;
    int nt = 2 * np + (comp >> 1);
    int n = tile * 128 + h * 64 + nt * 8 + (lane >> 2);
    int k = c * 32 + ks * 8 + (lane & 3) + (comp & 1) * 4;
    dst[e] = f2tf(src[(size_t)n * K + k]);
}

// ---------------------------------------------------------------------------
// Swapped MMA over one 32-K sub-chunk: A [k][pos] stride LDA_P, packed B half.
// warp tile 32(pos) x 64(ch): acc[2][8][4]
// ---------------------------------------------------------------------------
__device__ __forceinline__ void warp_mma_s(const float* sA, const float* sBh,
                                           float acc[2][8][4],
                                           int wm, int lane) {
    int grp = lane >> 2, tg = lane & 3;
#pragma unroll
    for (int ks = 0; ks < 4; ks++) {
        float a[2][4];
#pragma unroll
        for (int mt = 0; mt < 2; mt++) {
            const float* ap = sA + (ks * 8 + tg) * LDA_P + wm * 32 + mt * 16 + grp;
            a[mt][0] = ap[0];
            a[mt][1] = ap[8];
            a[mt][2] = ap[4 * LDA_P];
            a[mt][3] = ap[4 * LDA_P + 8];
        }
#pragma unroll
        for (int np = 0; np < 4; np++) {
            float4 bv = *(const float4*)(sBh + (ks * 4 + np) * 128 + lane * 4);
#pragma unroll
            for (int mt = 0; mt < 2; mt++) {
                asm volatile(
                    "mma.sync.aligned.m16n8k8.row.col.f32.tf32.tf32.f32 "
                    "{%0,%1,%2,%3}, {%4,%5,%6,%7}, {%8,%9}, {%0,%1,%2,%3};\n"
                    : "+f"(acc[mt][2 * np][0]), "+f"(acc[mt][2 * np][1]),
                      "+f"(acc[mt][2 * np][2]), "+f"(acc[mt][2 * np][3])
                    : "r"(__float_as_uint(a[mt][0])), "r"(__float_as_uint(a[mt][1])),
                      "r"(__float_as_uint(a[mt][2])), "r"(__float_as_uint(a[mt][3])),
                      "r"(__float_as_uint(bv.x)), "r"(__float_as_uint(bv.y)));
            }
#pragma unroll
            for (int mt = 0; mt < 2; mt++) {
                asm volatile(
                    "mma.sync.aligned.m16n8k8.row.col.f32.tf32.tf32.f32 "
                    "{%0,%1,%2,%3}, {%4,%5,%6,%7}, {%8,%9}, {%0,%1,%2,%3};\n"
                    : "+f"(acc[mt][2 * np + 1][0]), "+f"(acc[mt][2 * np + 1][1]),
                      "+f"(acc[mt][2 * np + 1][2]), "+f"(acc[mt][2 * np + 1][3])
                    : "r"(__float_as_uint(a[mt][0])), "r"(__float_as_uint(a[mt][1])),
                      "r"(__float_as_uint(a[mt][2])), "r"(__float_as_uint(a[mt][3])),
                      "r"(__float_as_uint(bv.z)), "r"(__float_as_uint(bv.w)));
            }
        }
    }
}

// flash variant (unchanged): A row-major stride FLDQ, warp tile 32x32
__device__ __forceinline__ void warp_mma_f(const float* A, const float* sB,
                                           float acc[2][4][4],
                                           int wm, int wn, int lane) {
    int grp = lane >> 2, tg = lane & 3;
#pragma unroll
    for (int ks = 0; ks < 4; ks++) {
        int kk = ks * 8;
        uint32_t a[2][4];
#pragma unroll
        for (int mt = 0; mt < 2; mt++) {
            const float* base = A + (wm + mt * 16 + grp) * FLDQ + kk + tg;
            a[mt][0] = __float_as_uint(base[0]);
            a[mt][1] = __float_as_uint(base[8 * FLDQ]);
            a[mt][2] = __float_as_uint(base[4]);
            a[mt][3] = __float_as_uint(base[8 * FLDQ + 4]);
        }
#pragma unroll
        for (int nt = 0; nt < 4; nt++) {
            const float* bb = sB + (kk + tg) * LDB + wn + nt * 8 + grp;
            uint32_t b0 = __float_as_uint(bb[0]);
            uint32_t b1 = __float_as_uint(bb[4 * LDB]);
#pragma unroll
            for (int mt = 0; mt < 2; mt++) {
                asm volatile(
                    "mma.sync.aligned.m16n8k8.row.col.f32.tf32.tf32.f32 "
                    "{%0,%1,%2,%3}, {%4,%5,%6,%7}, {%8,%9}, {%0,%1,%2,%3};\n"
                    : "+f"(acc[mt][nt][0]), "+f"(acc[mt][nt][1]),
                      "+f"(acc[mt][nt][2]), "+f"(acc[mt][nt][3])
                    : "r"(a[mt][0]), "r"(a[mt][1]), "r"(a[mt][2]), "r"(a[mt][3]),
                      "r"(b0), "r"(b1));
            }
        }
    }
}

// ---------------------------------------------------------------------------
// GEMM mainloop: 3-stage cp.async pipeline, K-chunk 64, 1 barrier per chunk.
// Aact: activations [ch][pos] (row stride HW). Bw: packed weights for this
// 128-ch tile; a K-64 chunk c occupies floats [c*8192, (c+1)*8192).
// ---------------------------------------------------------------------------
__device__ __forceinline__ void gemm_mainloop64(
    float* smp, const float* __restrict__ Aact, const float* __restrict__ Bw,
    int nchunks, float acc[2][8][4], int wm, int wh, int lane, int tid) {
    float* sA = smp;
    float* sB = smp + 3 * A_ST;

    auto load_stage = [&](int c) {
        int s = c % 3;
        float* dA = sA + s * A_ST;
        const float* srcA = Aact + (size_t)(c * 64) * HW;
#pragma unroll
        for (int i = 0; i < 8; i++) {
            int g = tid + i * 256, k = g >> 5, pq = (g & 31) * 4;
            cp16(dA + k * LDA_P + pq, srcA + (size_t)k * HW + pq);
        }
        float* dB = sB + s * B_ST;
        const float* srcB = Bw + (size_t)c * B_ST;
#pragma unroll
        for (int i = 0; i < 8; i++)
            cp16(dB + tid * 4 + i * 1024, srcB + tid * 4 + i * 1024);
        CP_COMMIT;
    };

    load_stage(0);
    load_stage(1);
    for (int c = 0; c < nchunks; c++) {
        if (c == nchunks - 1) { CP_WAIT0; } else { CP_WAIT1; }
        __syncthreads();
        if (c + 2 < nchunks) load_stage(c + 2);
        const float* cA = sA + (c % 3) * A_ST;
        const float* cB = sB + (c % 3) * B_ST;
#pragma unroll
        for (int s = 0; s < 2; s++)
            warp_mma_s(cA + s * 32 * LDA_P, cB + s * 4096 + wh * 2048, acc, wm, lane);
    }
}

// ---------------------------------------------------------------------------
// GEMM1: out1[ch][pos] = tf32(relu(BN(x^T @ w1^T)))   K=2048
// ---------------------------------------------------------------------------
__global__ __launch_bounds__(256, 1) void k_gemm1(
    const float* __restrict__ gamma, const float* __restrict__ beta,
    const float* __restrict__ mean, const float* __restrict__ var) {
    extern __shared__ float smp[];
    int n = blockIdx.z, p0 = blockIdx.x * 128, c0 = blockIdx.y * 128;
    int tid = threadIdx.x, lane = tid & 31, warp = tid >> 5;
    int wm = warp & 3, wh = warp >> 2;
    int grp = lane >> 2, tg = lane & 3;
    float acc[2][8][4] = {};
    gemm_mainloop64(smp, g_x + (size_t)n * CIN * HW + p0,
                    g_w1 + (size_t)blockIdx.y * (CIN * 128), CIN / 64,
                    acc, wm, wh, lane, tid);
    float* outb = g_out1 + (size_t)n * MID * HW;
#pragma unroll
    for (int nt = 0; nt < 8; nt++) {
        int ch = c0 + wh * 64 + nt * 8 + 2 * tg;
        float i0 = gamma[ch] * rsqrtf(var[ch] + BN_EPS);
        float b0 = beta[ch] - mean[ch] * i0;
        float i1 = gamma[ch + 1] * rsqrtf(var[ch + 1] + BN_EPS);
        float b1 = beta[ch + 1] - mean[ch + 1] * i1;
#pragma unroll
        for (int mt = 0; mt < 2; mt++) {
            int p = p0 + wm * 32 + mt * 16 + grp;
            float* a4 = acc[mt][nt];
            outb[(size_t)ch * HW + p]           = f2tf(fmaxf(a4[0] * i0 + b0, 0.f));
            outb[(size_t)(ch + 1) * HW + p]     = f2tf(fmaxf(a4[1] * i1 + b1, 0.f));
            outb[(size_t)ch * HW + p + 8]       = f2tf(fmaxf(a4[2] * i0 + b0, 0.f));
            outb[(size_t)(ch + 1) * HW + p + 8] = f2tf(fmaxf(a4[3] * i1 + b1, 0.f));
        }
    }
}

// ---------------------------------------------------------------------------
// GEMM2: q'/k'/v projections   N=1536 ch, K=512.  grid (8, 12, NB)
// ---------------------------------------------------------------------------
__global__ __launch_bounds__(256, 1) void k_gemm2(
    const float* __restrict__ pos_h, const float* __restrict__ pos_w) {
    extern __shared__ float smp[];
    int n = blockIdx.z, p0 = blockIdx.x * 128, c0 = blockIdx.y * 128;
    int tid = threadIdx.x, lane = tid & 31, warp = tid >> 5;
    int wm = warp & 3, wh = warp >> 2;
    int grp = lane >> 2, tg = lane & 3;
    float acc[2][8][4] = {};
    gemm_mainloop64(smp, g_out1 + (size_t)n * MID * HW + p0,
                    g_wqkv + (size_t)blockIdx.y * (MID * 128), MID / 64,
                    acc, wm, wh, lane, tid);
#pragma unroll
    for (int nt = 0; nt < 8; nt++) {
        int ch = c0 + wh * 64 + nt * 8 + 2 * tg;
#pragma unroll
        for (int mt = 0; mt < 2; mt++) {
            int p = p0 + wm * 32 + mt * 16 + grp;
            float* a4 = acc[mt][nt];
            if (c0 < 512) {                          // q' = tf32(q * scale)
                float* q = g_qk + ((size_t)n * 1024 + ch) * HW;
                q[p]          = f2tf(a4[0] * ATT_SCALE);
                q[HW + p]     = f2tf(a4[1] * ATT_SCALE);
                q[p + 8]      = f2tf(a4[2] * ATT_SCALE);
                q[HW + p + 8] = f2tf(a4[3] * ATT_SCALE);
            } else if (c0 < 1024) {                  // k' = tf32(k + emb[y,d])
                int d0 = ch & 127, d1 = (ch + 1) & 127;
                float* q = g_qk + ((size_t)n * 1024 + ch) * HW;
                int pa = p, pb = p + 8;
                float e00 = pos_h[(pa >> 5) * DQK + d0] + pos_w[(pa & 31) * DQK + d0];
                float e01 = pos_h[(pa >> 5) * DQK + d1] + pos_w[(pa & 31) * DQK + d1];
                float e10 = pos_h[(pb >> 5) * DQK + d0] + pos_w[(pb & 31) * DQK + d0];
                float e11 = pos_h[(pb >> 5) * DQK + d1] + pos_w[(pb & 31) * DQK + d1];
                q[pa]          = f2tf(a4[0] + e00);
                q[HW + pa]     = f2tf(a4[1] + e01);
                q[pb]          = f2tf(a4[2] + e10);
                q[HW + pb]     = f2tf(a4[3] + e11);
            } else {                                 // v -> g_vT[y][ch]
                int d = ch - 1024;
                float* v0 = g_vT + ((size_t)n * HW + p) * MID + d;
                float* v1 = g_vT + ((size_t)n * HW + p + 8) * MID + d;
                *(float2*)v0 = make_float2(f2tf(a4[0]), f2tf(a4[1]));
                *(float2*)v1 = make_float2(f2tf(a4[2]), f2tf(a4[3]));
            }
        }
    }
}

// ---------------------------------------------------------------------------
// Flash attention: x-tile 128, 512 threads, 3-buffer cp.async K/V ring.
// ---------------------------------------------------------------------------
__global__ __launch_bounds__(512) void k_flash() {
    extern __shared__ float sm[];
    float* Qs    = sm;
    float* Ss    = sm + F_S;
    float* sBr   = sm + F_B;
    float* sm_m  = sm + F_M;
    float* sm_l  = sm + F_L;
    float* sm_sc = sm + F_SC;

    int z = blockIdx.z, n = z >> 2, head = z & 3;
    int x0 = blockIdx.x * 128;
    int tid = threadIdx.x, lane = tid & 31, warp = tid >> 5;
    int wm = (warp & 3) * 32, wn = (warp >> 2) * 32;
    int grp = lane >> 2, tg = lane & 3;

    const float* qp = g_qk + ((size_t)n * 1024 + head * DQK) * HW;
    const float* kp = qp + (size_t)512 * HW;
    const float* vp = g_vT + (size_t)n * HW * MID + head * DQK;

    auto load_chunk = [&](int t) {
        float* buf = sBr + (t % 3) * BSZ;
        int j = t >> 3, ph = t & 7;
        const float* src;
        int ld;
        if (ph < 4) { src = kp + ((size_t)ph * 32) * HW + j * 128; ld = HW; }
        else        { src = vp + ((size_t)(j * 128 + (ph - 4) * 32)) * MID; ld = MID; }
#pragma unroll
        for (int i = 0; i < 2; i++) {
            int g = tid + i * 512, k = g >> 5, nq = (g & 31) * 4;
            cp16(buf + k * LDB + nq, src + (size_t)k * ld + nq);
        }
    };

    load_chunk(0); CP_COMMIT;
    load_chunk(1); CP_COMMIT;

#pragma unroll
    for (int i = 0; i < 8; i++) {
        int g = tid + i * 512;
        int d = g >> 5, xq = (g & 31) * 4;
        float4 v = *(const float4*)(qp + (size_t)d * HW + x0 + xq);
        Qs[(xq + 0) * FLDQ + d] = v.x;
        Qs[(xq + 1) * FLDQ + d] = v.y;
        Qs[(xq + 2) * FLDQ + d] = v.z;
        Qs[(xq + 3) * FLDQ + d] = v.w;
    }
    if (tid < 128) { sm_m[tid] = -1e30f; sm_l[tid] = 0.f; }
    float acc_o[2][4][4] = {};
    float acc_s[2][4][4] = {};
    __syncthreads();

    for (int j = 0; j < 8; j++) {
        for (int c = 0; c < 4; c++) {
            int t = j * 8 + c;
            if (t == 63) { CP_WAIT0; } else { CP_WAIT1; }
            __syncthreads();
            if (t + 2 < 64) { load_chunk(t + 2); CP_COMMIT; }
            warp_mma_f(Qs + c * 32, sBr + (t % 3) * BSZ, acc_s, wm, wn, lane);
        }
        __syncthreads();
#pragma unroll
        for (int mt = 0; mt < 2; mt++) {
            int r0 = wm + mt * 16 + grp, r1 = r0 + 8;
#pragma unroll
            for (int nt = 0; nt < 4; nt++) {
                int c = wn + nt * 8 + 2 * tg;
                Ss[r0 * FLDQ + c]     = acc_s[mt][nt][0];
                Ss[r0 * FLDQ + c + 1] = acc_s[mt][nt][1];
                Ss[r1 * FLDQ + c]     = acc_s[mt][nt][2];
                Ss[r1 * FLDQ + c + 1] = acc_s[mt][nt][3];
                acc_s[mt][nt][0] = acc_s[mt][nt][1] = 0.f;
                acc_s[mt][nt][2] = acc_s[mt][nt][3] = 0.f;
            }
        }
        __syncthreads();
        {
            int r = tid >> 2, q = tid & 3;
            float* row = Ss + r * FLDQ;
            float mloc = -1e30f;
#pragma unroll
            for (int i = 0; i < 32; i++) mloc = fmaxf(mloc, row[q + 4 * i]);
            mloc = fmaxf(mloc, __shfl_xor_sync(0xffffffff, mloc, 1));
            mloc = fmaxf(mloc, __shfl_xor_sync(0xffffffff, mloc, 2));
            float m_old = sm_m[r];
            float m_new = fmaxf(m_old, mloc);
            float s = 0.f;
#pragma unroll
            for (int i = 0; i < 32; i++) {
                float p = __expf(row[q + 4 * i] - m_new);
                row[q + 4 * i] = f2tf(p);
                s += p;
            }
            s += __shfl_xor_sync(0xffffffff, s, 1);
            s += __shfl_xor_sync(0xffffffff, s, 2);
            if (q == 0) {
                sm_sc[r] = __expf(m_old - m_new);
                sm_m[r]  = m_new;
                sm_l[r]  = sm_l[r] * sm_sc[r] + s;
            }
        }
        __syncthreads();
#pragma unroll
        for (int mt = 0; mt < 2; mt++) {
            int r0 = wm + mt * 16 + grp;
            float s0 = sm_sc[r0], s1 = sm_sc[r0 + 8];
#pragma unroll
            for (int nt = 0; nt < 4; nt++) {
                acc_o[mt][nt][0] *= s0; acc_o[mt][nt][1] *= s0;
                acc_o[mt][nt][2] *= s1; acc_o[mt][nt][3] *= s1;
            }
        }
        for (int c = 0; c < 4; c++) {
            int t = j * 8 + 4 + c;
            if (t == 63) { CP_WAIT0; } else { CP_WAIT1; }
            __syncthreads();
            if (t + 2 < 64) { load_chunk(t + 2); CP_COMMIT; }
            warp_mma_f(Ss + c * 32, sBr + (t % 3) * BSZ, acc_o, wm, wn, lane);
        }
    }

    __syncthreads();
#pragma unroll
    for (int mt = 0; mt < 2; mt++) {
        int r0 = wm + mt * 16 + grp, r1 = r0 + 8;
        float l0 = 1.f / sm_l[r0], l1 = 1.f / sm_l[r1];
#pragma unroll
        for (int nt = 0; nt < 4; nt++) {
            int c = wn + nt * 8 + 2 * tg;
            Ss[r0 * FLDQ + c]     = fmaxf(acc_o[mt][nt][0] * l0, 0.f);
            Ss[r0 * FLDQ + c + 1] = fmaxf(acc_o[mt][nt][1] * l0, 0.f);
            Ss[r1 * FLDQ + c]     = fmaxf(acc_o[mt][nt][2] * l1, 0.f);
            Ss[r1 * FLDQ + c + 1] = fmaxf(acc_o[mt][nt][3] * l1, 0.f);
        }
    }
    __syncthreads();
    float* op = g_attn + ((size_t)n * MID + head * DQK) * HW;
#pragma unroll
    for (int i = 0; i < 32; i++) {
        int g = tid + i * 512;
        int d = g >> 7, xo = g & 127;
        op[(size_t)d * HW + x0 + xo] = f2tf(Ss[xo * FLDQ + d]);
    }
}

// ---------------------------------------------------------------------------
// GEMM3: out[ch][pos] = relu(BN(attn^T @ w3^T) + x)   N=2048 ch, K=512
// ---------------------------------------------------------------------------
__global__ __launch_bounds__(256, 1) void k_gemm3(
    const float* __restrict__ gamma, const float* __restrict__ beta,
    const float* __restrict__ mean, const float* __restrict__ var,
    const float* __restrict__ x, float* __restrict__ out) {
    extern __shared__ float smp[];
    int n = blockIdx.z, p0 = blockIdx.x * 128, c0 = blockIdx.y * 128;
    int tid = threadIdx.x, lane = tid & 31, warp = tid >> 5;
    int wm = warp & 3, wh = warp >> 2;
    int grp = lane >> 2, tg = lane & 3;
    float acc[2][8][4] = {};
    gemm_mainloop64(smp, g_attn + (size_t)n * MID * HW + p0,
                    g_w3 + (size_t)blockIdx.y * (MID * 128), MID / 64,
                    acc, wm, wh, lane, tid);
#pragma unroll
    for (int nt = 0; nt < 8; nt++) {
        int ch = c0 + wh * 64 + nt * 8 + 2 * tg;
        float i0 = gamma[ch] * rsqrtf(var[ch] + BN_EPS);
        float b0 = beta[ch] - mean[ch] * i0;
        float i1 = gamma[ch + 1] * rsqrtf(var[ch + 1] + BN_EPS);
        float b1 = beta[ch + 1] - mean[ch + 1] * i1;
#pragma unroll
        for (int mt = 0; mt < 2; mt++) {
            int p = p0 + wm * 32 + mt * 16 + grp;
            float* a4 = acc[mt][nt];
            size_t e0 = (size_t)n * CIN * HW + (size_t)ch * HW + p;
            size_t e1 = e0 + HW;
            out[e0]     = fmaxf(a4[0] * i0 + b0 + x[e0], 0.f);
            out[e1]     = fmaxf(a4[1] * i1 + b1 + x[e1], 0.f);
            out[e0 + 8] = fmaxf(a4[2] * i0 + b0 + x[e0 + 8], 0.f);
            out[e1 + 8] = fmaxf(a4[3] * i1 + b1 + x[e1 + 8], 0.f);
        }
    }
}

// ---------------------------------------------------------------------------
extern "C" void kernel_launch(void* const* d_in, const int* in_sizes, int n_in,
                              void* d_out, int out_size) {
    const float* x       = (const float*)d_in[0];
    const float* conv1_w = (const float*)d_in[1];
    const float* gamma1  = (const float*)d_in[2];
    const float* beta1   = (const float*)d_in[3];
    const float* mean1   = (const float*)d_in[4];
    const float* var1    = (const float*)d_in[5];
    const float* qk_w    = (const float*)d_in[6];
    const float* v_w     = (const float*)d_in[7];
    const float* pos_h   = (const float*)d_in[8];
    const float* pos_w   = (const float*)d_in[9];
    const float* conv3_w = (const float*)d_in[10];
    const float* gamma3  = (const float*)d_in[11];
    const float* beta3   = (const float*)d_in[12];
    const float* mean3   = (const float*)d_in[13];
    const float* var3    = (const float*)d_in[14];
    float* out = (float*)d_out;

    cudaFuncSetAttribute(k_flash, cudaFuncAttributeMaxDynamicSharedMemorySize,
                         FLASH_SMEM);
    cudaFuncSetAttribute(k_gemm1, cudaFuncAttributeMaxDynamicSharedMemorySize,
                         GEMM_SMEM);
    cudaFuncSetAttribute(k_gemm2, cudaFuncAttributeMaxDynamicSharedMemorySize,
                         GEMM_SMEM);
    cudaFuncSetAttribute(k_gemm3, cudaFuncAttributeMaxDynamicSharedMemorySize,
                         GEMM_SMEM);

    float *p_x, *p_w1, *p_wqkv, *p_w3;
    cudaGetSymbolAddress((void**)&p_x, g_x);
    cudaGetSymbolAddress((void**)&p_w1, g_w1);
    cudaGetSymbolAddress((void**)&p_wqkv, g_wqkv);
    cudaGetSymbolAddress((void**)&p_w3, g_w3);

    dim3 blk256(256);
    {
        int n4 = NB * CIN * HW / 4;
        k_round<<<(n4 + 255) / 256, blk256>>>((const float4*)x, (float4*)p_x, n4);
    }
    k_repack<<<(MID * CIN + 255) / 256, blk256>>>(conv1_w, p_w1, MID, CIN);
    k_repack<<<(1024 * MID + 255) / 256, blk256>>>(qk_w, p_wqkv, 1024, MID);
    k_repack<<<(512 * MID + 255) / 256, blk256>>>(v_w, p_wqkv + (size_t)1024 * MID,
                                                  512, MID);
    k_repack<<<(CIN * MID + 255) / 256, blk256>>>(conv3_w, p_w3, CIN, MID);

    k_gemm1<<<dim3(8, 4, NB), blk256, GEMM_SMEM>>>(gamma1, beta1, mean1, var1);
    k_gemm2<<<dim3(8, 12, NB), blk256, GEMM_SMEM>>>(pos_h, pos_w);
    k_flash<<<dim3(8, 1, NB * NHEAD), dim3(512), FLASH_SMEM>>>();
    k_gemm3<<<dim3(8, 16, NB), blk256, GEMM_SMEM>>>(gamma3, beta3, mean3, var3, x, out);
}

// round 10
// speedup vs baseline: 1.4198x; 1.4198x over previous
#include <cuda_runtime.h>
#include <cuda_bf16.h>
#include <cstdint>
#include <cstddef>

// Problem constants
#define NB   16
#define CIN  2048
#define MID  512
#define HW   1024
#define DQK  128
#define NHEAD 4
#define ATT_SCALE 0.08838834764831845f
#define BN_EPS 1e-5f

// bf16 GEMM tile: block 128(pos) x 128(ch), K-chunk 32 (16 bf16x2 rows),
// 8 warps of 32(pos)x64(ch), 3-stage cp.async
#define LDA2 136                        // uint32 per A smem row (conflict-free)
#define A_ST2 (16 * LDA2)               // 2176 uint32 per A stage
#define B_ST2 2048                      // uint32 per packed-B stage
#define GEMM_SMEM ((3 * A_ST2 + 3 * B_ST2) * 4)   // 50688 B

// Flash tile config (tf32 path, unchanged from R7): x-tile 128, 512 threads
#define LDB  136
#define BSZ (32 * LDB)
#define FLDQ 132
#define F_S  (128 * FLDQ)
#define F_B  (2 * F_S)
#define F_M  (F_B + 3 * BSZ)
#define F_L  (F_M + 128)
#define F_SC (F_L + 128)
#define FLASH_SMEM ((F_SC + 128) * 4)  // 188928 B

// Scratch (device globals — allocation-free kernel_launch)
__device__ uint32_t g_x2   [(size_t)NB * (CIN / 2) * HW];  // x bf16x2 [n][ch2][pos]
__device__ uint32_t g_out12[(size_t)NB * (MID / 2) * HW];  // out1 bf16x2 [n][ch2][pos]
__device__ float    g_qk   [(size_t)NB * 1024 * HW];       // q'[d][x], k'[d][y] fp32(tf32)
__device__ float    g_vT   [(size_t)NB * HW * MID];        // v [n][y][ch] fp32(tf32)
__device__ uint32_t g_attn2[(size_t)NB * (MID / 2) * HW];  // attn bf16x2 [n][ch2][pos]
__device__ uint32_t g_w1u  [(size_t)MID * CIN / 2];        // packed bf16 B-fragments
__device__ uint32_t g_wqkvu[(size_t)1536 * MID / 2];
__device__ uint32_t g_w3u  [(size_t)CIN * MID / 2];

// ---------------------------------------------------------------------------
__device__ __forceinline__ float f2tf(float f) {
    uint32_t u;
    asm("cvt.rna.tf32.f32 %0, %1;" : "=r"(u) : "f"(f));
    return __uint_as_float(u);
}

// pack (lo, hi) floats into bf16x2 register (lo = lower k index)
__device__ __forceinline__ uint32_t bfpack(float lo, float hi) {
    uint32_t r;
    asm("cvt.rn.bf16x2.f32 %0, %1, %2;" : "=r"(r) : "f"(hi), "f"(lo));
    return r;
}

__device__ __forceinline__ void cp16f(float* dst, const float* src) {
    uint32_t d = (uint32_t)__cvta_generic_to_shared(dst);
    asm volatile("cp.async.cg.shared.global [%0], [%1], 16;\n" :: "r"(d), "l"(src));
}
__device__ __forceinline__ void cp16u(uint32_t* dst, const uint32_t* src) {
    uint32_t d = (uint32_t)__cvta_generic_to_shared(dst);
    asm volatile("cp.async.cg.shared.global [%0], [%1], 16;\n" :: "r"(d), "l"(src));
}
#define CP_COMMIT asm volatile("cp.async.commit_group;\n" ::: "memory")
#define CP_WAIT0  asm volatile("cp.async.wait_group 0;\n" ::: "memory")
#define CP_WAIT1  asm volatile("cp.async.wait_group 1;\n" ::: "memory")

// ---------------------------------------------------------------------------
// x -> bf16x2 pair layout [n][ch2][pos]
// ---------------------------------------------------------------------------
__global__ __launch_bounds__(256) void k_roundx(const float* __restrict__ x,
                                                uint32_t* __restrict__ dst) {
    size_t t = (size_t)blockIdx.x * 256 + threadIdx.x;   // NB*(CIN/2)*HW threads
    int pos = (int)(t & (HW - 1));
    size_t c2n = t >> 10;
    size_t base = (size_t)2 * c2n * HW + pos;
    dst[t] = bfpack(x[base], x[base + HW]);
}

// ---------------------------------------------------------------------------
// Weight repack into bf16 B-fragment order for m16n8k16.
// uint32 index e: [tile][c32][h][s][np][lane][comp]
//   comp: {nt-even b0, nt-even b1, nt-odd b0, nt-odd b1}
//   n = tile*128 + h*64 + (2np + comp>>1)*8 + (lane>>2)
//   kpair = c32*16 + s*8 + (lane&3) + (comp&1)*4 ; k = 2*kpair (+1)
// ---------------------------------------------------------------------------
__global__ __launch_bounds__(256) void k_repackb(const float* __restrict__ src,
                                                 uint32_t* __restrict__ dst,
                                                 int Mout, int K) {
    size_t e = (size_t)blockIdx.x * 256 + threadIdx.x;
    if (e >= (size_t)Mout * K / 2) return;
    int comp = (int)(e & 3);
    int lane = (int)((e >> 2) & 31);
    int np   = (int)((e >> 7) & 3);
    int s    = (int)((e >> 9) & 1);
    int h    = (int)((e >> 10) & 1);
    size_t rest = e >> 11;
    int nch = K >> 5;
    int c = (int)(rest % nch);
    size_t tile = rest / nch;
    int grp = lane >> 2, tg = lane & 3;
    int nt = 2 * np + (comp >> 1);
    size_t n = tile * 128 + h * 64 + nt * 8 + grp;
    int kp = c * 16 + s * 8 + tg + (comp & 1) * 4;
    dst[e] = bfpack(src[n * K + 2 * kp], src[n * K + 2 * kp + 1]);
}

// ---------------------------------------------------------------------------
// bf16 MMA over one 32-ch chunk: A [k2][pos] uint32, B packed.
// warp tile 32(pos) x 64(ch): acc[2][8][4]
// ---------------------------------------------------------------------------
__device__ __forceinline__ void warp_mma_b(const uint32_t* sA, const uint32_t* sBh,
                                           float acc[2][8][4], int wm, int lane) {
    int grp = lane >> 2, tg = lane & 3;
#pragma unroll
    for (int s = 0; s < 2; s++) {
        uint32_t a[2][4];
#pragma unroll
        for (int mt = 0; mt < 2; mt++) {
            const uint32_t* ap = sA + (s * 8 + tg) * LDA2 + wm * 32 + mt * 16 + grp;
            a[mt][0] = ap[0];
            a[mt][1] = ap[8];
            a[mt][2] = ap[4 * LDA2];
            a[mt][3] = ap[4 * LDA2 + 8];
        }
#pragma unroll
        for (int np = 0; np < 4; np++) {
            uint4 bv = *(const uint4*)(sBh + (s * 4 + np) * 128 + lane * 4);
#pragma unroll
            for (int mt = 0; mt < 2; mt++) {
                asm volatile(
                    "mma.sync.aligned.m16n8k16.row.col.f32.bf16.bf16.f32 "
                    "{%0,%1,%2,%3}, {%4,%5,%6,%7}, {%8,%9}, {%0,%1,%2,%3};\n"
                    : "+f"(acc[mt][2 * np][0]), "+f"(acc[mt][2 * np][1]),
                      "+f"(acc[mt][2 * np][2]), "+f"(acc[mt][2 * np][3])
                    : "r"(a[mt][0]), "r"(a[mt][1]), "r"(a[mt][2]), "r"(a[mt][3]),
                      "r"(bv.x), "r"(bv.y));
            }
#pragma unroll
            for (int mt = 0; mt < 2; mt++) {
                asm volatile(
                    "mma.sync.aligned.m16n8k16.row.col.f32.bf16.bf16.f32 "
                    "{%0,%1,%2,%3}, {%4,%5,%6,%7}, {%8,%9}, {%0,%1,%2,%3};\n"
                    : "+f"(acc[mt][2 * np + 1][0]), "+f"(acc[mt][2 * np + 1][1]),
                      "+f"(acc[mt][2 * np + 1][2]), "+f"(acc[mt][2 * np + 1][3])
                    : "r"(a[mt][0]), "r"(a[mt][1]), "r"(a[mt][2]), "r"(a[mt][3]),
                      "r"(bv.z), "r"(bv.w));
            }
        }
    }
}

// ---------------------------------------------------------------------------
// bf16 GEMM mainloop: 3-stage cp.async, K-chunk 32, 2 CTAs/SM.
// Aact: activations bf16x2 [ch2][pos] rows (stride HW uint32).
// Bw: packed weights for this 128-ch tile (2048 uint32 per chunk).
// ---------------------------------------------------------------------------
__device__ __forceinline__ void gemm_loop(
    uint32_t* smp, const uint32_t* __restrict__ Aact,
    const uint32_t* __restrict__ Bw, int nchunks,
    float acc[2][8][4], int wm, int wh, int lane, int tid) {
    uint32_t* sA = smp;
    uint32_t* sB = smp + 3 * A_ST2;
    auto load_stage = [&](int c) {
        int st = c % 3;
        uint32_t* dA = sA + st * A_ST2;
        const uint32_t* srcA = Aact + (size_t)(c * 16) * HW;
#pragma unroll
        for (int i = 0; i < 2; i++) {
            int g = tid + i * 256, k = g >> 5, pq = (g & 31) * 4;
            cp16u(dA + k * LDA2 + pq, srcA + (size_t)k * HW + pq);
        }
        uint32_t* dB = sB + st * B_ST2;
        const uint32_t* srcB = Bw + (size_t)c * B_ST2;
#pragma unroll
        for (int i = 0; i < 2; i++)
            cp16u(dB + tid * 4 + i * 1024, srcB + tid * 4 + i * 1024);
        CP_COMMIT;
    };
    load_stage(0);
    load_stage(1);
    for (int c = 0; c < nchunks; c++) {
        if (c == nchunks - 1) { CP_WAIT0; } else { CP_WAIT1; }
        __syncthreads();
        if (c + 2 < nchunks) load_stage(c + 2);
        warp_mma_b(sA + (c % 3) * A_ST2, sB + (c % 3) * B_ST2 + wh * 1024,
                   acc, wm, lane);
    }
}

// ---------------------------------------------------------------------------
// GEMM1: out1 = bf16(relu(BN(x^T @ w1^T)))   K=2048.  grid (8, 4, NB)
// ---------------------------------------------------------------------------
__global__ __launch_bounds__(256, 2) void k_gemm1(
    const float* __restrict__ gamma, const float* __restrict__ beta,
    const float* __restrict__ mean, const float* __restrict__ var) {
    extern __shared__ uint32_t smp[];
    int n = blockIdx.z, p0 = blockIdx.x * 128, c0 = blockIdx.y * 128;
    int tid = threadIdx.x, lane = tid & 31, warp = tid >> 5;
    int wm = warp & 3, wh = warp >> 2;
    int grp = lane >> 2, tg = lane & 3;
    float acc[2][8][4] = {};
    gemm_loop(smp, g_x2 + (size_t)n * (CIN / 2) * HW + p0,
              g_w1u + (size_t)blockIdx.y * (CIN * 64), CIN / 32,
              acc, wm, wh, lane, tid);
    uint32_t* out2 = g_out12 + (size_t)n * (MID / 2) * HW;
#pragma unroll
    for (int nt = 0; nt < 8; nt++) {
        int ch = c0 + wh * 64 + nt * 8 + 2 * tg;
        float i0 = gamma[ch] * rsqrtf(var[ch] + BN_EPS);
        float b0 = beta[ch] - mean[ch] * i0;
        float i1 = gamma[ch + 1] * rsqrtf(var[ch + 1] + BN_EPS);
        float b1 = beta[ch + 1] - mean[ch + 1] * i1;
#pragma unroll
        for (int mt = 0; mt < 2; mt++) {
            int p = p0 + wm * 32 + mt * 16 + grp;
            float* a4 = acc[mt][nt];
            size_t row = (size_t)(ch >> 1) * HW;
            out2[row + p]     = bfpack(fmaxf(a4[0] * i0 + b0, 0.f),
                                       fmaxf(a4[1] * i1 + b1, 0.f));
            out2[row + p + 8] = bfpack(fmaxf(a4[2] * i0 + b0, 0.f),
                                       fmaxf(a4[3] * i1 + b1, 0.f));
        }
    }
}

// ---------------------------------------------------------------------------
// GEMM2: q'/k'/v projections   N=1536 ch, K=512.  grid (8, 12, NB)
// q'/k' -> g_qk fp32 (tf32-rounded); v -> g_vT fp32 (tf32-rounded)
// ---------------------------------------------------------------------------
__global__ __launch_bounds__(256, 2) void k_gemm2(
    const float* __restrict__ pos_h, const float* __restrict__ pos_w) {
    extern __shared__ uint32_t smp[];
    int n = blockIdx.z, p0 = blockIdx.x * 128, c0 = blockIdx.y * 128;
    int tid = threadIdx.x, lane = tid & 31, warp = tid >> 5;
    int wm = warp & 3, wh = warp >> 2;
    int grp = lane >> 2, tg = lane & 3;
    float acc[2][8][4] = {};
    gemm_loop(smp, g_out12 + (size_t)n * (MID / 2) * HW + p0,
              g_wqkvu + (size_t)blockIdx.y * (MID * 64), MID / 32,
              acc, wm, wh, lane, tid);
#pragma unroll
    for (int nt = 0; nt < 8; nt++) {
        int ch = c0 + wh * 64 + nt * 8 + 2 * tg;
#pragma unroll
        for (int mt = 0; mt < 2; mt++) {
            int p = p0 + wm * 32 + mt * 16 + grp;
            float* a4 = acc[mt][nt];
            if (c0 < 512) {                          // q' = tf32(q * scale)
                float* q = g_qk + ((size_t)n * 1024 + ch) * HW;
                q[p]          = f2tf(a4[0] * ATT_SCALE);
                q[HW + p]     = f2tf(a4[1] * ATT_SCALE);
                q[p + 8]      = f2tf(a4[2] * ATT_SCALE);
                q[HW + p + 8] = f2tf(a4[3] * ATT_SCALE);
            } else if (c0 < 1024) {                  // k' = tf32(k + emb[y,d])
                int d0 = ch & 127, d1 = (ch + 1) & 127;
                float* q = g_qk + ((size_t)n * 1024 + ch) * HW;
                int pa = p, pb = p + 8;
                float e00 = pos_h[(pa >> 5) * DQK + d0] + pos_w[(pa & 31) * DQK + d0];
                float e01 = pos_h[(pa >> 5) * DQK + d1] + pos_w[(pa & 31) * DQK + d1];
                float e10 = pos_h[(pb >> 5) * DQK + d0] + pos_w[(pb & 31) * DQK + d0];
                float e11 = pos_h[(pb >> 5) * DQK + d1] + pos_w[(pb & 31) * DQK + d1];
                q[pa]      = f2tf(a4[0] + e00);
                q[HW + pa] = f2tf(a4[1] + e01);
                q[pb]      = f2tf(a4[2] + e10);
                q[HW + pb] = f2tf(a4[3] + e11);
            } else {                                 // v -> g_vT[y][ch]
                int d = ch - 1024;
                float* v0 = g_vT + ((size_t)n * HW + p) * MID + d;
                float* v1 = g_vT + ((size_t)n * HW + p + 8) * MID + d;
                *(float2*)v0 = make_float2(f2tf(a4[0]), f2tf(a4[1]));
                *(float2*)v1 = make_float2(f2tf(a4[2]), f2tf(a4[3]));
            }
        }
    }
}

// ---------------------------------------------------------------------------
// Flash attention (tf32, identical to R7 except final store -> g_attn2 bf16x2)
// ---------------------------------------------------------------------------
__device__ __forceinline__ void warp_mma_f(const float* A, const float* sB,
                                           float acc[2][4][4],
                                           int wm, int wn, int lane) {
    int grp = lane >> 2, tg = lane & 3;
#pragma unroll
    for (int ks = 0; ks < 4; ks++) {
        int kk = ks * 8;
        uint32_t a[2][4];
#pragma unroll
        for (int mt = 0; mt < 2; mt++) {
            const float* base = A + (wm + mt * 16 + grp) * FLDQ + kk + tg;
            a[mt][0] = __float_as_uint(base[0]);
            a[mt][1] = __float_as_uint(base[8 * FLDQ]);
            a[mt][2] = __float_as_uint(base[4]);
            a[mt][3] = __float_as_uint(base[8 * FLDQ + 4]);
        }
#pragma unroll
        for (int nt = 0; nt < 4; nt++) {
            const float* bb = sB + (kk + tg) * LDB + wn + nt * 8 + grp;
            uint32_t b0 = __float_as_uint(bb[0]);
            uint32_t b1 = __float_as_uint(bb[4 * LDB]);
#pragma unroll
            for (int mt = 0; mt < 2; mt++) {
                asm volatile(
                    "mma.sync.aligned.m16n8k8.row.col.f32.tf32.tf32.f32 "
                    "{%0,%1,%2,%3}, {%4,%5,%6,%7}, {%8,%9}, {%0,%1,%2,%3};\n"
                    : "+f"(acc[mt][nt][0]), "+f"(acc[mt][nt][1]),
                      "+f"(acc[mt][nt][2]), "+f"(acc[mt][nt][3])
                    : "r"(a[mt][0]), "r"(a[mt][1]), "r"(a[mt][2]), "r"(a[mt][3]),
                      "r"(b0), "r"(b1));
            }
        }
    }
}

__global__ __launch_bounds__(512) void k_flash() {
    extern __shared__ float sm[];
    float* Qs    = sm;
    float* Ss    = sm + F_S;
    float* sBr   = sm + F_B;
    float* sm_m  = sm + F_M;
    float* sm_l  = sm + F_L;
    float* sm_sc = sm + F_SC;

    int z = blockIdx.z, n = z >> 2, head = z & 3;
    int x0 = blockIdx.x * 128;
    int tid = threadIdx.x, lane = tid & 31, warp = tid >> 5;
    int wm = (warp & 3) * 32, wn = (warp >> 2) * 32;
    int grp = lane >> 2, tg = lane & 3;

    const float* qp = g_qk + ((size_t)n * 1024 + head * DQK) * HW;
    const float* kp = qp + (size_t)512 * HW;
    const float* vp = g_vT + (size_t)n * HW * MID + head * DQK;

    auto load_chunk = [&](int t) {
        float* buf = sBr + (t % 3) * BSZ;
        int j = t >> 3, ph = t & 7;
        const float* src;
        int ld;
        if (ph < 4) { src = kp + ((size_t)ph * 32) * HW + j * 128; ld = HW; }
        else        { src = vp + ((size_t)(j * 128 + (ph - 4) * 32)) * MID; ld = MID; }
#pragma unroll
        for (int i = 0; i < 2; i++) {
            int g = tid + i * 512, k = g >> 5, nq = (g & 31) * 4;
            cp16f(buf + k * LDB + nq, src + (size_t)k * ld + nq);
        }
    };

    load_chunk(0); CP_COMMIT;
    load_chunk(1); CP_COMMIT;

#pragma unroll
    for (int i = 0; i < 8; i++) {
        int g = tid + i * 512;
        int d = g >> 5, xq = (g & 31) * 4;
        float4 v = *(const float4*)(qp + (size_t)d * HW + x0 + xq);
        Qs[(xq + 0) * FLDQ + d] = v.x;
        Qs[(xq + 1) * FLDQ + d] = v.y;
        Qs[(xq + 2) * FLDQ + d] = v.z;
        Qs[(xq + 3) * FLDQ + d] = v.w;
    }
    if (tid < 128) { sm_m[tid] = -1e30f; sm_l[tid] = 0.f; }
    float acc_o[2][4][4] = {};
    float acc_s[2][4][4] = {};
    __syncthreads();

    for (int j = 0; j < 8; j++) {
        for (int c = 0; c < 4; c++) {
            int t = j * 8 + c;
            if (t == 63) { CP_WAIT0; } else { CP_WAIT1; }
            __syncthreads();
            if (t + 2 < 64) { load_chunk(t + 2); CP_COMMIT; }
            warp_mma_f(Qs + c * 32, sBr + (t % 3) * BSZ, acc_s, wm, wn, lane);
        }
        __syncthreads();
#pragma unroll
        for (int mt = 0; mt < 2; mt++) {
            int r0 = wm + mt * 16 + grp, r1 = r0 + 8;
#pragma unroll
            for (int nt = 0; nt < 4; nt++) {
                int c = wn + nt * 8 + 2 * tg;
                Ss[r0 * FLDQ + c]     = acc_s[mt][nt][0];
                Ss[r0 * FLDQ + c + 1] = acc_s[mt][nt][1];
                Ss[r1 * FLDQ + c]     = acc_s[mt][nt][2];
                Ss[r1 * FLDQ + c + 1] = acc_s[mt][nt][3];
                acc_s[mt][nt][0] = acc_s[mt][nt][1] = 0.f;
                acc_s[mt][nt][2] = acc_s[mt][nt][3] = 0.f;
            }
        }
        __syncthreads();
        {
            int r = tid >> 2, q = tid & 3;
            float* row = Ss + r * FLDQ;
            float mloc = -1e30f;
#pragma unroll
            for (int i = 0; i < 32; i++) mloc = fmaxf(mloc, row[q + 4 * i]);
            mloc = fmaxf(mloc, __shfl_xor_sync(0xffffffff, mloc, 1));
            mloc = fmaxf(mloc, __shfl_xor_sync(0xffffffff, mloc, 2));
            float m_old = sm_m[r];
            float m_new = fmaxf(m_old, mloc);
            float s = 0.f;
#pragma unroll
            for (int i = 0; i < 32; i++) {
                float p = __expf(row[q + 4 * i] - m_new);
                row[q + 4 * i] = f2tf(p);
                s += p;
            }
            s += __shfl_xor_sync(0xffffffff, s, 1);
            s += __shfl_xor_sync(0xffffffff, s, 2);
            if (q == 0) {
                sm_sc[r] = __expf(m_old - m_new);
                sm_m[r]  = m_new;
                sm_l[r]  = sm_l[r] * sm_sc[r] + s;
            }
        }
        __syncthreads();
#pragma unroll
        for (int mt = 0; mt < 2; mt++) {
            int r0 = wm + mt * 16 + grp;
            float s0 = sm_sc[r0], s1 = sm_sc[r0 + 8];
#pragma unroll
            for (int nt = 0; nt < 4; nt++) {
                acc_o[mt][nt][0] *= s0; acc_o[mt][nt][1] *= s0;
                acc_o[mt][nt][2] *= s1; acc_o[mt][nt][3] *= s1;
            }
        }
        for (int c = 0; c < 4; c++) {
            int t = j * 8 + 4 + c;
            if (t == 63) { CP_WAIT0; } else { CP_WAIT1; }
            __syncthreads();
            if (t + 2 < 64) { load_chunk(t + 2); CP_COMMIT; }
            warp_mma_f(Ss + c * 32, sBr + (t % 3) * BSZ, acc_o, wm, wn, lane);
        }
    }

    __syncthreads();
#pragma unroll
    for (int mt = 0; mt < 2; mt++) {
        int r0 = wm + mt * 16 + grp, r1 = r0 + 8;
        float l0 = 1.f / sm_l[r0], l1 = 1.f / sm_l[r1];
#pragma unroll
        for (int nt = 0; nt < 4; nt++) {
            int c = wn + nt * 8 + 2 * tg;
            Ss[r0 * FLDQ + c]     = fmaxf(acc_o[mt][nt][0] * l0, 0.f);
            Ss[r0 * FLDQ + c + 1] = fmaxf(acc_o[mt][nt][1] * l0, 0.f);
            Ss[r1 * FLDQ + c]     = fmaxf(acc_o[mt][nt][2] * l1, 0.f);
            Ss[r1 * FLDQ + c + 1] = fmaxf(acc_o[mt][nt][3] * l1, 0.f);
        }
    }
    __syncthreads();
    // store bf16x2 pairs along d into g_attn2 [n][ch2][pos]
    uint32_t* op2 = g_attn2 + ((size_t)n * (MID / 2) + head * (DQK / 2)) * HW;
#pragma unroll
    for (int i = 0; i < 16; i++) {
        int g = tid + i * 512;               // 8192 = 64 d2 * 128 x
        int d2 = g >> 7, xo = g & 127;
        op2[(size_t)d2 * HW + x0 + xo] =
            bfpack(Ss[xo * FLDQ + 2 * d2], Ss[xo * FLDQ + 2 * d2 + 1]);
    }
}

// ---------------------------------------------------------------------------
// GEMM3: out[ch][pos] = relu(BN(attn^T @ w3^T) + x)   N=2048 ch, K=512
// grid (8, 16, NB)
// ---------------------------------------------------------------------------
__global__ __launch_bounds__(256, 2) void k_gemm3(
    const float* __restrict__ gamma, const float* __restrict__ beta,
    const float* __restrict__ mean, const float* __restrict__ var,
    const float* __restrict__ x, float* __restrict__ out) {
    extern __shared__ uint32_t smp[];
    int n = blockIdx.z, p0 = blockIdx.x * 128, c0 = blockIdx.y * 128;
    int tid = threadIdx.x, lane = tid & 31, warp = tid >> 5;
    int wm = warp & 3, wh = warp >> 2;
    int grp = lane >> 2, tg = lane & 3;
    float acc[2][8][4] = {};
    gemm_loop(smp, g_attn2 + (size_t)n * (MID / 2) * HW + p0,
              g_w3u + (size_t)blockIdx.y * (MID * 64), MID / 32,
              acc, wm, wh, lane, tid);
#pragma unroll
    for (int nt = 0; nt < 8; nt++) {
        int ch = c0 + wh * 64 + nt * 8 + 2 * tg;
        float i0 = gamma[ch] * rsqrtf(var[ch] + BN_EPS);
        float b0 = beta[ch] - mean[ch] * i0;
        float i1 = gamma[ch + 1] * rsqrtf(var[ch + 1] + BN_EPS);
        float b1 = beta[ch + 1] - mean[ch + 1] * i1;
#pragma unroll
        for (int mt = 0; mt < 2; mt++) {
            int p = p0 + wm * 32 + mt * 16 + grp;
            float* a4 = acc[mt][nt];
            size_t e0 = (size_t)n * CIN * HW + (size_t)ch * HW + p;
            size_t e1 = e0 + HW;
            out[e0]     = fmaxf(a4[0] * i0 + b0 + x[e0], 0.f);
            out[e1]     = fmaxf(a4[1] * i1 + b1 + x[e1], 0.f);
            out[e0 + 8] = fmaxf(a4[2] * i0 + b0 + x[e0 + 8], 0.f);
            out[e1 + 8] = fmaxf(a4[3] * i1 + b1 + x[e1 + 8], 0.f);
        }
    }
}

// ---------------------------------------------------------------------------
extern "C" void kernel_launch(void* const* d_in, const int* in_sizes, int n_in,
                              void* d_out, int out_size) {
    const float* x       = (const float*)d_in[0];
    const float* conv1_w = (const float*)d_in[1];
    const float* gamma1  = (const float*)d_in[2];
    const float* beta1   = (const float*)d_in[3];
    const float* mean1   = (const float*)d_in[4];
    const float* var1    = (const float*)d_in[5];
    const float* qk_w    = (const float*)d_in[6];
    const float* v_w     = (const float*)d_in[7];
    const float* pos_h   = (const float*)d_in[8];
    const float* pos_w   = (const float*)d_in[9];
    const float* conv3_w = (const float*)d_in[10];
    const float* gamma3  = (const float*)d_in[11];
    const float* beta3   = (const float*)d_in[12];
    const float* mean3   = (const float*)d_in[13];
    const float* var3    = (const float*)d_in[14];
    float* out = (float*)d_out;

    cudaFuncSetAttribute(k_flash, cudaFuncAttributeMaxDynamicSharedMemorySize,
                         FLASH_SMEM);
    cudaFuncSetAttribute(k_gemm1, cudaFuncAttributeMaxDynamicSharedMemorySize,
                         GEMM_SMEM);
    cudaFuncSetAttribute(k_gemm2, cudaFuncAttributeMaxDynamicSharedMemorySize,
                         GEMM_SMEM);
    cudaFuncSetAttribute(k_gemm3, cudaFuncAttributeMaxDynamicSharedMemorySize,
                         GEMM_SMEM);

    uint32_t *p_x2, *p_w1, *p_wqkv, *p_w3;
    cudaGetSymbolAddress((void**)&p_x2, g_x2);
    cudaGetSymbolAddress((void**)&p_w1, g_w1u);
    cudaGetSymbolAddress((void**)&p_wqkv, g_wqkvu);
    cudaGetSymbolAddress((void**)&p_w3, g_w3u);

    dim3 blk256(256);
    // x -> bf16x2 pair layout
    {
        size_t nt = (size_t)NB * (CIN / 2) * HW;
        k_roundx<<<(unsigned)(nt / 256), blk256>>>(x, p_x2);
    }
    // weight repack into bf16 B-fragment order
    k_repackb<<<(MID * CIN / 2 + 255) / 256, blk256>>>(conv1_w, p_w1, MID, CIN);
    k_repackb<<<(1024 * MID / 2 + 255) / 256, blk256>>>(qk_w, p_wqkv, 1024, MID);
    k_repackb<<<(512 * MID / 2 + 255) / 256, blk256>>>(v_w,
                                                       p_wqkv + (size_t)1024 * MID / 2,
                                                       512, MID);
    k_repackb<<<(CIN * MID / 2 + 255) / 256, blk256>>>(conv3_w, p_w3, CIN, MID);

    k_gemm1<<<dim3(8, 4, NB), blk256, GEMM_SMEM>>>(gamma1, beta1, mean1, var1);
    k_gemm2<<<dim3(8, 12, NB), blk256, GEMM_SMEM>>>(pos_h, pos_w);
    k_flash<<<dim3(8, 1, NB * NHEAD), dim3(512), FLASH_SMEM>>>();
    k_gemm3<<<dim3(8, 16, NB), blk256, GEMM_SMEM>>>(gamma3, beta3, mean3, var3, x, out);
}

// round 11
// speedup vs baseline: 1.5333x; 1.0800x over previous
#include <cuda_runtime.h>
#include <cuda_bf16.h>
#include <cstdint>
#include <cstddef>

// Problem constants
#define NB   16
#define CIN  2048
#define MID  512
#define HW   1024
#define DQK  128
#define NHEAD 4
#define ATT_SCALE 0.08838834764831845f
#define BN_EPS 1e-5f

// bf16 GEMM tile: block 128(pos) x 128(ch), K-chunk 32 (16 bf16x2 rows),
// 8 warps of 32(pos)x64(ch), 3-stage cp.async
#define LDA2 136
#define A_ST2 (16 * LDA2)
#define B_ST2 2048
#define GEMM_SMEM ((3 * A_ST2 + 3 * B_ST2) * 4)   // 50688 B

// Flash (bf16) smem layout, uint32 units
#define QLD 68
#define Q_SZ (128 * QLD)            // 8704
#define P_OFF Q_SZ
#define P_SZ (128 * QLD)            // 8704 (PLD == QLD)
#define R_OFF (P_OFF + P_SZ)        // 17408
#define CLD 136
#define CH_SZ (16 * CLD)            // 2176 u32 per K/V chunk
#define S_OFF_U (R_OFF + 3 * CH_SZ) // 23936
#define SLD 132
#define S_SZ (128 * SLD)            // 16896 (fp32 region)
#define M_OFF (S_OFF_U + S_SZ)      // 40832
#define L_OFF (M_OFF + 128)
#define SC_OFF2 (L_OFF + 128)
#define FLASH_SMEM ((SC_OFF2 + 128) * 4)   // 164864 B

// Scratch (device globals — allocation-free kernel_launch)
__device__ uint32_t g_x2   [(size_t)NB * (CIN / 2) * HW];  // x bf16x2 [n][ch2][pos]
__device__ uint32_t g_out12[(size_t)NB * (MID / 2) * HW];  // out1 bf16x2
__device__ uint32_t g_qk2  [(size_t)NB * 512 * HW];        // q'/k' bf16x2 [n][d2][pos]
__device__ float    g_vT   [(size_t)NB * HW * MID];        // v fp32 [n][y][ch]
__device__ uint32_t g_v2   [(size_t)NB * 512 * 512];       // v bf16x2 [n][y2][ch]
__device__ uint32_t g_attn2[(size_t)NB * (MID / 2) * HW];  // attn bf16x2
__device__ uint32_t g_w1u  [(size_t)MID * CIN / 2];
__device__ uint32_t g_wqkvu[(size_t)1536 * MID / 2];
__device__ uint32_t g_w3u  [(size_t)CIN * MID / 2];

// ---------------------------------------------------------------------------
__device__ __forceinline__ uint32_t bfpack(float lo, float hi) {
    uint32_t r;
    asm("cvt.rn.bf16x2.f32 %0, %1, %2;" : "=r"(r) : "f"(hi), "f"(lo));
    return r;
}

__device__ __forceinline__ void cp16u(uint32_t* dst, const uint32_t* src) {
    uint32_t d = (uint32_t)__cvta_generic_to_shared(dst);
    asm volatile("cp.async.cg.shared.global [%0], [%1], 16;\n" :: "r"(d), "l"(src));
}
#define CP_COMMIT asm volatile("cp.async.commit_group;\n" ::: "memory")
#define CP_WAIT0  asm volatile("cp.async.wait_group 0;\n" ::: "memory")
#define CP_WAIT1  asm volatile("cp.async.wait_group 1;\n" ::: "memory")

// bf16 m16n8k16 MMA
#define MMA_BF16(acc4, a0, a1, a2, a3, b0, b1) \
    asm volatile( \
        "mma.sync.aligned.m16n8k16.row.col.f32.bf16.bf16.f32 " \
        "{%0,%1,%2,%3}, {%4,%5,%6,%7}, {%8,%9}, {%0,%1,%2,%3};\n" \
        : "+f"((acc4)[0]), "+f"((acc4)[1]), "+f"((acc4)[2]), "+f"((acc4)[3]) \
        : "r"(a0), "r"(a1), "r"(a2), "r"(a3), "r"(b0), "r"(b1))

// ---------------------------------------------------------------------------
// x -> bf16x2 pair layout [n][ch2][pos]
// ---------------------------------------------------------------------------
__global__ __launch_bounds__(256) void k_roundx(const float* __restrict__ x,
                                                uint32_t* __restrict__ dst) {
    size_t t = (size_t)blockIdx.x * 256 + threadIdx.x;
    int pos = (int)(t & (HW - 1));
    size_t c2n = t >> 10;
    size_t base = (size_t)2 * c2n * HW + pos;
    dst[t] = bfpack(x[base], x[base + HW]);
}

// v fp32 [n][y][512] -> bf16x2 pairs along y: g_v2[n][y2][512]
__global__ __launch_bounds__(256) void k_packv() {
    size_t t = (size_t)blockIdx.x * 256 + threadIdx.x;   // NB*512*512
    int d = (int)(t & 511);
    size_t y2n = t >> 9;            // n*512 + y2
    size_t n = y2n >> 9;
    int y2 = (int)(y2n & 511);
    const float* src = g_vT + ((size_t)n * 1024 + 2 * y2) * 512 + d;
    g_v2[t] = bfpack(src[0], src[512]);
}

// ---------------------------------------------------------------------------
// Weight repack into bf16 B-fragment order for m16n8k16 (same as R9).
// ---------------------------------------------------------------------------
__global__ __launch_bounds__(256) void k_repackb(const float* __restrict__ src,
                                                 uint32_t* __restrict__ dst,
                                                 int Mout, int K) {
    size_t e = (size_t)blockIdx.x * 256 + threadIdx.x;
    if (e >= (size_t)Mout * K / 2) return;
    int comp = (int)(e & 3);
    int lane = (int)((e >> 2) & 31);
    int np   = (int)((e >> 7) & 3);
    int s    = (int)((e >> 9) & 1);
    int h    = (int)((e >> 10) & 1);
    size_t rest = e >> 11;
    int nch = K >> 5;
    int c = (int)(rest % nch);
    size_t tile = rest / nch;
    int grp = lane >> 2, tg = lane & 3;
    int nt = 2 * np + (comp >> 1);
    size_t n = tile * 128 + h * 64 + nt * 8 + grp;
    int kp = c * 16 + s * 8 + tg + (comp & 1) * 4;
    dst[e] = bfpack(src[n * K + 2 * kp], src[n * K + 2 * kp + 1]);
}

// ---------------------------------------------------------------------------
// bf16 GEMM MMA chunk (identical to R9)
// ---------------------------------------------------------------------------
__device__ __forceinline__ void warp_mma_b(const uint32_t* sA, const uint32_t* sBh,
                                           float acc[2][8][4], int wm, int lane) {
    int grp = lane >> 2, tg = lane & 3;
#pragma unroll
    for (int s = 0; s < 2; s++) {
        uint32_t a[2][4];
#pragma unroll
        for (int mt = 0; mt < 2; mt++) {
            const uint32_t* ap = sA + (s * 8 + tg) * LDA2 + wm * 32 + mt * 16 + grp;
            a[mt][0] = ap[0];
            a[mt][1] = ap[8];
            a[mt][2] = ap[4 * LDA2];
            a[mt][3] = ap[4 * LDA2 + 8];
        }
#pragma unroll
        for (int np = 0; np < 4; np++) {
            uint4 bv = *(const uint4*)(sBh + (s * 4 + np) * 128 + lane * 4);
#pragma unroll
            for (int mt = 0; mt < 2; mt++)
                MMA_BF16(acc[mt][2 * np], a[mt][0], a[mt][1], a[mt][2], a[mt][3],
                         bv.x, bv.y);
#pragma unroll
            for (int mt = 0; mt < 2; mt++)
                MMA_BF16(acc[mt][2 * np + 1], a[mt][0], a[mt][1], a[mt][2], a[mt][3],
                         bv.z, bv.w);
        }
    }
}

__device__ __forceinline__ void gemm_loop(
    uint32_t* smp, const uint32_t* __restrict__ Aact,
    const uint32_t* __restrict__ Bw, int nchunks,
    float acc[2][8][4], int wm, int wh, int lane, int tid) {
    uint32_t* sA = smp;
    uint32_t* sB = smp + 3 * A_ST2;
    auto load_stage = [&](int c) {
        int st = c % 3;
        uint32_t* dA = sA + st * A_ST2;
        const uint32_t* srcA = Aact + (size_t)(c * 16) * HW;
#pragma unroll
        for (int i = 0; i < 2; i++) {
            int g = tid + i * 256, k = g >> 5, pq = (g & 31) * 4;
            cp16u(dA + k * LDA2 + pq, srcA + (size_t)k * HW + pq);
        }
        uint32_t* dB = sB + st * B_ST2;
        const uint32_t* srcB = Bw + (size_t)c * B_ST2;
#pragma unroll
        for (int i = 0; i < 2; i++)
            cp16u(dB + tid * 4 + i * 1024, srcB + tid * 4 + i * 1024);
        CP_COMMIT;
    };
    load_stage(0);
    load_stage(1);
    for (int c = 0; c < nchunks; c++) {
        if (c == nchunks - 1) { CP_WAIT0; } else { CP_WAIT1; }
        __syncthreads();
        if (c + 2 < nchunks) load_stage(c + 2);
        warp_mma_b(sA + (c % 3) * A_ST2, sB + (c % 3) * B_ST2 + wh * 1024,
                   acc, wm, lane);
    }
}

// ---------------------------------------------------------------------------
// GEMM1: out1 = bf16(relu(BN(x^T @ w1^T)))   K=2048.  grid (8, 4, NB)
// ---------------------------------------------------------------------------
__global__ __launch_bounds__(256, 2) void k_gemm1(
    const float* __restrict__ gamma, const float* __restrict__ beta,
    const float* __restrict__ mean, const float* __restrict__ var) {
    extern __shared__ uint32_t smp[];
    int n = blockIdx.z, p0 = blockIdx.x * 128, c0 = blockIdx.y * 128;
    int tid = threadIdx.x, lane = tid & 31, warp = tid >> 5;
    int wm = warp & 3, wh = warp >> 2;
    int grp = lane >> 2, tg = lane & 3;
    float acc[2][8][4] = {};
    gemm_loop(smp, g_x2 + (size_t)n * (CIN / 2) * HW + p0,
              g_w1u + (size_t)blockIdx.y * (CIN * 64), CIN / 32,
              acc, wm, wh, lane, tid);
    uint32_t* out2 = g_out12 + (size_t)n * (MID / 2) * HW;
#pragma unroll
    for (int nt = 0; nt < 8; nt++) {
        int ch = c0 + wh * 64 + nt * 8 + 2 * tg;
        float i0 = gamma[ch] * rsqrtf(var[ch] + BN_EPS);
        float b0 = beta[ch] - mean[ch] * i0;
        float i1 = gamma[ch + 1] * rsqrtf(var[ch + 1] + BN_EPS);
        float b1 = beta[ch + 1] - mean[ch + 1] * i1;
#pragma unroll
        for (int mt = 0; mt < 2; mt++) {
            int p = p0 + wm * 32 + mt * 16 + grp;
            float* a4 = acc[mt][nt];
            size_t row = (size_t)(ch >> 1) * HW;
            out2[row + p]     = bfpack(fmaxf(a4[0] * i0 + b0, 0.f),
                                       fmaxf(a4[1] * i1 + b1, 0.f));
            out2[row + p + 8] = bfpack(fmaxf(a4[2] * i0 + b0, 0.f),
                                       fmaxf(a4[3] * i1 + b1, 0.f));
        }
    }
}

// ---------------------------------------------------------------------------
// GEMM2: q'/k' -> g_qk2 bf16x2 packed along d; v -> g_vT fp32.  grid (8,12,NB)
// ---------------------------------------------------------------------------
__global__ __launch_bounds__(256, 2) void k_gemm2(
    const float* __restrict__ pos_h, const float* __restrict__ pos_w) {
    extern __shared__ uint32_t smp[];
    int n = blockIdx.z, p0 = blockIdx.x * 128, c0 = blockIdx.y * 128;
    int tid = threadIdx.x, lane = tid & 31, warp = tid >> 5;
    int wm = warp & 3, wh = warp >> 2;
    int grp = lane >> 2, tg = lane & 3;
    float acc[2][8][4] = {};
    gemm_loop(smp, g_out12 + (size_t)n * (MID / 2) * HW + p0,
              g_wqkvu + (size_t)blockIdx.y * (MID * 64), MID / 32,
              acc, wm, wh, lane, tid);
#pragma unroll
    for (int nt = 0; nt < 8; nt++) {
        int ch = c0 + wh * 64 + nt * 8 + 2 * tg;      // even
#pragma unroll
        for (int mt = 0; mt < 2; mt++) {
            int p = p0 + wm * 32 + mt * 16 + grp;
            float* a4 = acc[mt][nt];
            if (c0 < 512) {                          // q' pairs (d, d+1)
                uint32_t* q = g_qk2 + ((size_t)n * 512 + (ch >> 1)) * HW;
                q[p]     = bfpack(a4[0] * ATT_SCALE, a4[1] * ATT_SCALE);
                q[p + 8] = bfpack(a4[2] * ATT_SCALE, a4[3] * ATT_SCALE);
            } else if (c0 < 1024) {                  // k' = k + emb, pairs (d, d+1)
                int d0 = ch & 127, d1 = (ch + 1) & 127;
                uint32_t* q = g_qk2 + ((size_t)n * 512 + (ch >> 1)) * HW;
                int pa = p, pb = p + 8;
                float e00 = pos_h[(pa >> 5) * DQK + d0] + pos_w[(pa & 31) * DQK + d0];
                float e01 = pos_h[(pa >> 5) * DQK + d1] + pos_w[(pa & 31) * DQK + d1];
                float e10 = pos_h[(pb >> 5) * DQK + d0] + pos_w[(pb & 31) * DQK + d0];
                float e11 = pos_h[(pb >> 5) * DQK + d1] + pos_w[(pb & 31) * DQK + d1];
                q[pa] = bfpack(a4[0] + e00, a4[1] + e01);
                q[pb] = bfpack(a4[2] + e10, a4[3] + e11);
            } else {                                 // v -> g_vT[y][ch] fp32
                int d = ch - 1024;
                float* v0 = g_vT + ((size_t)n * HW + p) * MID + d;
                float* v1 = g_vT + ((size_t)n * HW + p + 8) * MID + d;
                *(float2*)v0 = make_float2(a4[0], a4[1]);
                *(float2*)v1 = make_float2(a4[2], a4[3]);
            }
        }
    }
}

// ---------------------------------------------------------------------------
// Flash attention, bf16 MMAs: x-tile 128, 512 threads, 3-buffer cp.async ring.
// ---------------------------------------------------------------------------
__device__ __forceinline__ void warp_mma_fb(const uint32_t* A, int cbase,
                                            const uint32_t* B,
                                            float acc[2][4][4],
                                            int wm, int wn, int lane) {
    int grp = lane >> 2, tg = lane & 3;
#pragma unroll
    for (int ks = 0; ks < 2; ks++) {
        int kk = ks * 8;
        uint32_t a[2][4];
#pragma unroll
        for (int mt = 0; mt < 2; mt++) {
            const uint32_t* ap = A + (wm + mt * 16 + grp) * QLD + cbase + kk + tg;
            a[mt][0] = ap[0];
            a[mt][1] = ap[8 * QLD];
            a[mt][2] = ap[4];
            a[mt][3] = ap[8 * QLD + 4];
        }
#pragma unroll
        for (int nt = 0; nt < 4; nt++) {
            uint32_t b0 = B[(kk + tg) * CLD + wn + nt * 8 + grp];
            uint32_t b1 = B[(kk + 4 + tg) * CLD + wn + nt * 8 + grp];
#pragma unroll
            for (int mt = 0; mt < 2; mt++)
                MMA_BF16(acc[mt][nt], a[mt][0], a[mt][1], a[mt][2], a[mt][3], b0, b1);
        }
    }
}

__global__ __launch_bounds__(512) void k_flash() {
    extern __shared__ uint32_t smu[];
    uint32_t* Qs    = smu;                       // [128 x][QLD d2]
    uint32_t* Pp    = smu + P_OFF;               // [128 x][QLD y2]
    uint32_t* ring  = smu + R_OFF;               // 3 x [16][CLD]
    float*    Ssf   = (float*)(smu + S_OFF_U);   // [128 x][SLD y] fp32
    float*    sm_m  = (float*)(smu + M_OFF);
    float*    sm_l  = (float*)(smu + L_OFF);
    float*    sm_sc = (float*)(smu + SC_OFF2);

    int z = blockIdx.z, n = z >> 2, head = z & 3;
    int x0 = blockIdx.x * 128;
    int tid = threadIdx.x, lane = tid & 31, warp = tid >> 5;
    int wm = (warp & 3) * 32, wn = (warp >> 2) * 32;
    int grp = lane >> 2, tg = lane & 3;

    const uint32_t* qp2 = g_qk2 + ((size_t)n * 512 + head * 64) * HW;   // q' [64 d2][1024 x]
    const uint32_t* kp2 = qp2 + (size_t)256 * HW;                       // k' [64 d2][1024 y]
    const uint32_t* v2p = g_v2 + (size_t)n * 512 * 512 + head * 128;    // [512 y2][512 d] slice

    auto load_chunk = [&](int t) {
        uint32_t* buf = ring + (t % 3) * CH_SZ;
        int j = t >> 3, ph = t & 7;
        const uint32_t* src;
        size_t ld;
        if (ph < 4) { src = kp2 + (size_t)(ph * 16) * HW + j * 128; ld = HW; }
        else        { src = v2p + (size_t)(j * 64 + (ph - 4) * 16) * 512; ld = 512; }
        int k = tid >> 5, cq = (tid & 31) * 4;   // 16 rows x 32 quads = 512 threads
        cp16u(buf + k * CLD + cq, src + (size_t)k * ld + cq);
        CP_COMMIT;
    };

    load_chunk(0);
    load_chunk(1);

    // Q tile: [128 x][64 d2] transposed from [d2][x]
#pragma unroll
    for (int i = 0; i < 4; i++) {
        int g = tid + i * 512;                // 2048 uint4 reads
        int d2 = g >> 5, xq = (g & 31) * 4;
        uint4 v = *(const uint4*)(qp2 + (size_t)d2 * HW + x0 + xq);
        Qs[(xq + 0) * QLD + d2] = v.x;
        Qs[(xq + 1) * QLD + d2] = v.y;
        Qs[(xq + 2) * QLD + d2] = v.z;
        Qs[(xq + 3) * QLD + d2] = v.w;
    }
    if (tid < 128) { sm_m[tid] = -1e30f; sm_l[tid] = 0.f; }
    float acc_o[2][4][4] = {};
    float acc_s[2][4][4] = {};
    __syncthreads();

    for (int j = 0; j < 8; j++) {
        // ---- S = Q @ K'^T : 4 chunks of 32 d (16 d2) ----
        for (int c = 0; c < 4; c++) {
            int t = j * 8 + c;
            if (t == 63) { CP_WAIT0; } else { CP_WAIT1; }
            __syncthreads();
            if (t + 2 < 64) load_chunk(t + 2);
            warp_mma_fb(Qs, c * 16, ring + (t % 3) * CH_SZ, acc_s, wm, wn, lane);
        }
        __syncthreads();
        // ---- write S (fp32), zero acc_s ----
#pragma unroll
        for (int mt = 0; mt < 2; mt++) {
            int r0 = wm + mt * 16 + grp, r1 = r0 + 8;
#pragma unroll
            for (int nt = 0; nt < 4; nt++) {
                int c = wn + nt * 8 + 2 * tg;
                Ssf[r0 * SLD + c]     = acc_s[mt][nt][0];
                Ssf[r0 * SLD + c + 1] = acc_s[mt][nt][1];
                Ssf[r1 * SLD + c]     = acc_s[mt][nt][2];
                Ssf[r1 * SLD + c + 1] = acc_s[mt][nt][3];
                acc_s[mt][nt][0] = acc_s[mt][nt][1] = 0.f;
                acc_s[mt][nt][2] = acc_s[mt][nt][3] = 0.f;
            }
        }
        __syncthreads();
        // ---- online softmax + bf16x2 pack of P ----
        {
            int r = tid >> 2, q = tid & 3;
            float* row = Ssf + r * SLD;
            float mloc = -1e30f;
#pragma unroll
            for (int i = 0; i < 32; i++) mloc = fmaxf(mloc, row[q + 4 * i]);
            mloc = fmaxf(mloc, __shfl_xor_sync(0xffffffff, mloc, 1));
            mloc = fmaxf(mloc, __shfl_xor_sync(0xffffffff, mloc, 2));
            float m_old = sm_m[r];
            float m_new = fmaxf(m_old, mloc);
            float s = 0.f;
            uint32_t* prow = Pp + r * QLD + (q >> 1);
#pragma unroll
            for (int i = 0; i < 32; i++) {
                float ev = __expf(row[q + 4 * i] - m_new);
                s += ev;
                float partner = __shfl_xor_sync(0xffffffff, ev, 1);
                if ((q & 1) == 0) prow[2 * i] = bfpack(ev, partner);
            }
            s += __shfl_xor_sync(0xffffffff, s, 1);
            s += __shfl_xor_sync(0xffffffff, s, 2);
            if (q == 0) {
                sm_sc[r] = __expf(m_old - m_new);
                sm_m[r]  = m_new;
                sm_l[r]  = sm_l[r] * sm_sc[r] + s;
            }
        }
        __syncthreads();
        // ---- rescale O ----
#pragma unroll
        for (int mt = 0; mt < 2; mt++) {
            int r0 = wm + mt * 16 + grp;
            float s0 = sm_sc[r0], s1 = sm_sc[r0 + 8];
#pragma unroll
            for (int nt = 0; nt < 4; nt++) {
                acc_o[mt][nt][0] *= s0; acc_o[mt][nt][1] *= s0;
                acc_o[mt][nt][2] *= s1; acc_o[mt][nt][3] *= s1;
            }
        }
        // ---- O += P @ V : 4 chunks of 32 y (16 y2) ----
        for (int c = 0; c < 4; c++) {
            int t = j * 8 + 4 + c;
            if (t == 63) { CP_WAIT0; } else { CP_WAIT1; }
            __syncthreads();
            if (t + 2 < 64) load_chunk(t + 2);
            warp_mma_fb(Pp, c * 16, ring + (t % 3) * CH_SZ, acc_o, wm, wn, lane);
        }
    }

    // ---- epilogue: O /= l, relu, transpose via Ssf, bf16x2 store ----
    __syncthreads();
#pragma unroll
    for (int mt = 0; mt < 2; mt++) {
        int r0 = wm + mt * 16 + grp, r1 = r0 + 8;
        float l0 = 1.f / sm_l[r0], l1 = 1.f / sm_l[r1];
#pragma unroll
        for (int nt = 0; nt < 4; nt++) {
            int c = wn + nt * 8 + 2 * tg;
            Ssf[r0 * SLD + c]     = fmaxf(acc_o[mt][nt][0] * l0, 0.f);
            Ssf[r0 * SLD + c + 1] = fmaxf(acc_o[mt][nt][1] * l0, 0.f);
            Ssf[r1 * SLD + c]     = fmaxf(acc_o[mt][nt][2] * l1, 0.f);
            Ssf[r1 * SLD + c + 1] = fmaxf(acc_o[mt][nt][3] * l1, 0.f);
        }
    }
    __syncthreads();
    uint32_t* op2 = g_attn2 + ((size_t)n * (MID / 2) + head * (DQK / 2)) * HW;
#pragma unroll
    for (int i = 0; i < 16; i++) {
        int g = tid + i * 512;               // 8192 = 64 d2 * 128 x
        int d2 = g >> 7, xo = g & 127;
        op2[(size_t)d2 * HW + x0 + xo] =
            bfpack(Ssf[xo * SLD + 2 * d2], Ssf[xo * SLD + 2 * d2 + 1]);
    }
}

// ---------------------------------------------------------------------------
// GEMM3: out[ch][pos] = relu(BN(attn^T @ w3^T) + x)   grid (8, 16, NB)
// ---------------------------------------------------------------------------
__global__ __launch_bounds__(256, 2) void k_gemm3(
    const float* __restrict__ gamma, const float* __restrict__ beta,
    const float* __restrict__ mean, const float* __restrict__ var,
    const float* __restrict__ x, float* __restrict__ out) {
    extern __shared__ uint32_t smp[];
    int n = blockIdx.z, p0 = blockIdx.x * 128, c0 = blockIdx.y * 128;
    int tid = threadIdx.x, lane = tid & 31, warp = tid >> 5;
    int wm = warp & 3, wh = warp >> 2;
    int grp = lane >> 2, tg = lane & 3;
    float acc[2][8][4] = {};
    gemm_loop(smp, g_attn2 + (size_t)n * (MID / 2) * HW + p0,
              g_w3u + (size_t)blockIdx.y * (MID * 64), MID / 32,
              acc, wm, wh, lane, tid);
#pragma unroll
    for (int nt = 0; nt < 8; nt++) {
        int ch = c0 + wh * 64 + nt * 8 + 2 * tg;
        float i0 = gamma[ch] * rsqrtf(var[ch] + BN_EPS);
        float b0 = beta[ch] - mean[ch] * i0;
        float i1 = gamma[ch + 1] * rsqrtf(var[ch + 1] + BN_EPS);
        float b1 = beta[ch + 1] - mean[ch + 1] * i1;
#pragma unroll
        for (int mt = 0; mt < 2; mt++) {
            int p = p0 + wm * 32 + mt * 16 + grp;
            float* a4 = acc[mt][nt];
            size_t e0 = (size_t)n * CIN * HW + (size_t)ch * HW + p;
            size_t e1 = e0 + HW;
            out[e0]     = fmaxf(a4[0] * i0 + b0 + x[e0], 0.f);
            out[e1]     = fmaxf(a4[1] * i1 + b1 + x[e1], 0.f);
            out[e0 + 8] = fmaxf(a4[2] * i0 + b0 + x[e0 + 8], 0.f);
            out[e1 + 8] = fmaxf(a4[3] * i1 + b1 + x[e1 + 8], 0.f);
        }
    }
}

// ---------------------------------------------------------------------------
extern "C" void kernel_launch(void* const* d_in, const int* in_sizes, int n_in,
                              void* d_out, int out_size) {
    const float* x       = (const float*)d_in[0];
    const float* conv1_w = (const float*)d_in[1];
    const float* gamma1  = (const float*)d_in[2];
    const float* beta1   = (const float*)d_in[3];
    const float* mean1   = (const float*)d_in[4];
    const float* var1    = (const float*)d_in[5];
    const float* qk_w    = (const float*)d_in[6];
    const float* v_w     = (const float*)d_in[7];
    const float* pos_h   = (const float*)d_in[8];
    const float* pos_w   = (const float*)d_in[9];
    const float* conv3_w = (const float*)d_in[10];
    const float* gamma3  = (const float*)d_in[11];
    const float* beta3   = (const float*)d_in[12];
    const float* mean3   = (const float*)d_in[13];
    const float* var3    = (const float*)d_in[14];
    float* out = (float*)d_out;

    cudaFuncSetAttribute(k_flash, cudaFuncAttributeMaxDynamicSharedMemorySize,
                         FLASH_SMEM);
    cudaFuncSetAttribute(k_gemm1, cudaFuncAttributeMaxDynamicSharedMemorySize,
                         GEMM_SMEM);
    cudaFuncSetAttribute(k_gemm2, cudaFuncAttributeMaxDynamicSharedMemorySize,
                         GEMM_SMEM);
    cudaFuncSetAttribute(k_gemm3, cudaFuncAttributeMaxDynamicSharedMemorySize,
                         GEMM_SMEM);

    uint32_t *p_x2, *p_w1, *p_wqkv, *p_w3;
    cudaGetSymbolAddress((void**)&p_x2, g_x2);
    cudaGetSymbolAddress((void**)&p_w1, g_w1u);
    cudaGetSymbolAddress((void**)&p_wqkv, g_wqkvu);
    cudaGetSymbolAddress((void**)&p_w3, g_w3u);

    dim3 blk256(256);
    {
        size_t nt = (size_t)NB * (CIN / 2) * HW;
        k_roundx<<<(unsigned)(nt / 256), blk256>>>(x, p_x2);
    }
    k_repackb<<<(MID * CIN / 2 + 255) / 256, blk256>>>(conv1_w, p_w1, MID, CIN);
    k_repackb<<<(1024 * MID / 2 + 255) / 256, blk256>>>(qk_w, p_wqkv, 1024, MID);
    k_repackb<<<(512 * MID / 2 + 255) / 256, blk256>>>(v_w,
                                                       p_wqkv + (size_t)1024 * MID / 2,
                                                       512, MID);
    k_repackb<<<(CIN * MID / 2 + 255) / 256, blk256>>>(conv3_w, p_w3, CIN, MID);

    k_gemm1<<<dim3(8, 4, NB), blk256, GEMM_SMEM>>>(gamma1, beta1, mean1, var1);
    k_gemm2<<<dim3(8, 12, NB), blk256, GEMM_SMEM>>>(pos_h, pos_w);
    {
        size_t nt = (size_t)NB * 512 * 512;
        k_packv<<<(unsigned)(nt / 256), blk256>>>();
    }
    k_flash<<<dim3(8, 1, NB * NHEAD), dim3(512), FLASH_SMEM>>>();
    k_gemm3<<<dim3(8, 16, NB), blk256, GEMM_SMEM>>>(gamma3, beta3, mean3, var3, x, out);
}

// round 12
// speedup vs baseline: 2.0002x; 1.3045x over previous
#include <cuda_runtime.h>
#include <cuda_bf16.h>
#include <cstdint>
#include <cstddef>

// Problem constants
#define NB   16
#define CIN  2048
#define MID  512
#define HW   1024
#define DQK  128
#define NHEAD 4
#define ATT_SCALE 0.08838834764831845f
#define BN_EPS 1e-5f

// bf16 GEMM tile: block 128(pos) x 128(ch), K-chunk 32 (16 bf16x2 rows),
// 8 warps of 32(pos)x64(ch), 3-stage cp.async
#define LDA2 136
#define A_ST2 (16 * LDA2)
#define B_ST2 2048
#define GEMM_SMEM ((3 * A_ST2 + 3 * B_ST2) * 4)   // 50688 B

// Flash (FA2-style): x-tile 64, 128 threads, 4 warps of 16(pos) x 128(y)
#define QLD 36                       // Qs row stride (u32), conflict-free
#define CLD 136                      // ring row stride (u32)
#define CH_SZ (16 * CLD)             // 2176 u32 per K/V chunk
#define OLD 68                       // O transpose buffer stride

// Scratch (device globals — allocation-free kernel_launch)
__device__ uint32_t g_x2   [(size_t)NB * (CIN / 2) * HW];  // x bf16x2 [n][ch2][pos]
__device__ uint32_t g_out12[(size_t)NB * (MID / 2) * HW];  // out1 bf16x2
__device__ uint32_t g_qk2  [(size_t)NB * 512 * HW];        // q'/k' bf16x2 [n][d2][pos]
__device__ uint32_t g_v2   [(size_t)NB * 512 * 512];       // v bf16x2 [n][y2][ch]
__device__ uint32_t g_attn2[(size_t)NB * (MID / 2) * HW];  // attn bf16x2
__device__ uint32_t g_w1u  [(size_t)MID * CIN / 2];
__device__ uint32_t g_wqkvu[(size_t)1536 * MID / 2];
__device__ uint32_t g_w3u  [(size_t)CIN * MID / 2];

// ---------------------------------------------------------------------------
__device__ __forceinline__ uint32_t bfpack(float lo, float hi) {
    uint32_t r;
    asm("cvt.rn.bf16x2.f32 %0, %1, %2;" : "=r"(r) : "f"(hi), "f"(lo));
    return r;
}

__device__ __forceinline__ void cp16u(uint32_t* dst, const uint32_t* src) {
    uint32_t d = (uint32_t)__cvta_generic_to_shared(dst);
    asm volatile("cp.async.cg.shared.global [%0], [%1], 16;\n" :: "r"(d), "l"(src));
}
#define CP_COMMIT asm volatile("cp.async.commit_group;\n" ::: "memory")
#define CP_WAIT0  asm volatile("cp.async.wait_group 0;\n" ::: "memory")
#define CP_WAIT1  asm volatile("cp.async.wait_group 1;\n" ::: "memory")

#define MMA_BF16(acc4, a0, a1, a2, a3, b0, b1) \
    asm volatile( \
        "mma.sync.aligned.m16n8k16.row.col.f32.bf16.bf16.f32 " \
        "{%0,%1,%2,%3}, {%4,%5,%6,%7}, {%8,%9}, {%0,%1,%2,%3};\n" \
        : "+f"((acc4)[0]), "+f"((acc4)[1]), "+f"((acc4)[2]), "+f"((acc4)[3]) \
        : "r"(a0), "r"(a1), "r"(a2), "r"(a3), "r"(b0), "r"(b1))

// ---------------------------------------------------------------------------
// x -> bf16x2 pair layout [n][ch2][pos]
// ---------------------------------------------------------------------------
__global__ __launch_bounds__(256) void k_roundx(const float* __restrict__ x,
                                                uint32_t* __restrict__ dst) {
    size_t t = (size_t)blockIdx.x * 256 + threadIdx.x;
    int pos = (int)(t & (HW - 1));
    size_t c2n = t >> 10;
    size_t base = (size_t)2 * c2n * HW + pos;
    dst[t] = bfpack(x[base], x[base + HW]);
}

// ---------------------------------------------------------------------------
// Weight repack into bf16 B-fragment order for m16n8k16.
// ---------------------------------------------------------------------------
__global__ __launch_bounds__(256) void k_repackb(const float* __restrict__ src,
                                                 uint32_t* __restrict__ dst,
                                                 int Mout, int K) {
    size_t e = (size_t)blockIdx.x * 256 + threadIdx.x;
    if (e >= (size_t)Mout * K / 2) return;
    int comp = (int)(e & 3);
    int lane = (int)((e >> 2) & 31);
    int np   = (int)((e >> 7) & 3);
    int s    = (int)((e >> 9) & 1);
    int h    = (int)((e >> 10) & 1);
    size_t rest = e >> 11;
    int nch = K >> 5;
    int c = (int)(rest % nch);
    size_t tile = rest / nch;
    int grp = lane >> 2, tg = lane & 3;
    int nt = 2 * np + (comp >> 1);
    size_t n = tile * 128 + h * 64 + nt * 8 + grp;
    int kp = c * 16 + s * 8 + tg + (comp & 1) * 4;
    dst[e] = bfpack(src[n * K + 2 * kp], src[n * K + 2 * kp + 1]);
}

// ---------------------------------------------------------------------------
// bf16 GEMM MMA chunk + mainloop (as R9/R10)
// ---------------------------------------------------------------------------
__device__ __forceinline__ void warp_mma_b(const uint32_t* sA, const uint32_t* sBh,
                                           float acc[2][8][4], int wm, int lane) {
    int grp = lane >> 2, tg = lane & 3;
#pragma unroll
    for (int s = 0; s < 2; s++) {
        uint32_t a[2][4];
#pragma unroll
        for (int mt = 0; mt < 2; mt++) {
            const uint32_t* ap = sA + (s * 8 + tg) * LDA2 + wm * 32 + mt * 16 + grp;
            a[mt][0] = ap[0];
            a[mt][1] = ap[8];
            a[mt][2] = ap[4 * LDA2];
            a[mt][3] = ap[4 * LDA2 + 8];
        }
#pragma unroll
        for (int np = 0; np < 4; np++) {
            uint4 bv = *(const uint4*)(sBh + (s * 4 + np) * 128 + lane * 4);
#pragma unroll
            for (int mt = 0; mt < 2; mt++)
                MMA_BF16(acc[mt][2 * np], a[mt][0], a[mt][1], a[mt][2], a[mt][3],
                         bv.x, bv.y);
#pragma unroll
            for (int mt = 0; mt < 2; mt++)
                MMA_BF16(acc[mt][2 * np + 1], a[mt][0], a[mt][1], a[mt][2], a[mt][3],
                         bv.z, bv.w);
        }
    }
}

__device__ __forceinline__ void gemm_loop(
    uint32_t* smp, const uint32_t* __restrict__ Aact,
    const uint32_t* __restrict__ Bw, int nchunks,
    float acc[2][8][4], int wm, int wh, int lane, int tid) {
    uint32_t* sA = smp;
    uint32_t* sB = smp + 3 * A_ST2;
    auto load_stage = [&](int c) {
        int st = c % 3;
        uint32_t* dA = sA + st * A_ST2;
        const uint32_t* srcA = Aact + (size_t)(c * 16) * HW;
#pragma unroll
        for (int i = 0; i < 2; i++) {
            int g = tid + i * 256, k = g >> 5, pq = (g & 31) * 4;
            cp16u(dA + k * LDA2 + pq, srcA + (size_t)k * HW + pq);
        }
        uint32_t* dB = sB + st * B_ST2;
        const uint32_t* srcB = Bw + (size_t)c * B_ST2;
#pragma unroll
        for (int i = 0; i < 2; i++)
            cp16u(dB + tid * 4 + i * 1024, srcB + tid * 4 + i * 1024);
        CP_COMMIT;
    };
    load_stage(0);
    load_stage(1);
    for (int c = 0; c < nchunks; c++) {
        if (c == nchunks - 1) { CP_WAIT0; } else { CP_WAIT1; }
        __syncthreads();
        if (c + 2 < nchunks) load_stage(c + 2);
        warp_mma_b(sA + (c % 3) * A_ST2, sB + (c % 3) * B_ST2 + wh * 1024,
                   acc, wm, lane);
    }
}

// ---------------------------------------------------------------------------
// GEMM1: out1 = bf16(relu(BN(x^T @ w1^T)))   K=2048.  grid (8, 4, NB)
// ---------------------------------------------------------------------------
__global__ __launch_bounds__(256, 2) void k_gemm1(
    const float* __restrict__ gamma, const float* __restrict__ beta,
    const float* __restrict__ mean, const float* __restrict__ var) {
    extern __shared__ uint32_t smp[];
    int n = blockIdx.z, p0 = blockIdx.x * 128, c0 = blockIdx.y * 128;
    int tid = threadIdx.x, lane = tid & 31, warp = tid >> 5;
    int wm = warp & 3, wh = warp >> 2;
    int grp = lane >> 2, tg = lane & 3;
    float acc[2][8][4] = {};
    gemm_loop(smp, g_x2 + (size_t)n * (CIN / 2) * HW + p0,
              g_w1u + (size_t)blockIdx.y * (CIN * 64), CIN / 32,
              acc, wm, wh, lane, tid);
    uint32_t* out2 = g_out12 + (size_t)n * (MID / 2) * HW;
#pragma unroll
    for (int nt = 0; nt < 8; nt++) {
        int ch = c0 + wh * 64 + nt * 8 + 2 * tg;
        float i0 = gamma[ch] * rsqrtf(var[ch] + BN_EPS);
        float b0 = beta[ch] - mean[ch] * i0;
        float i1 = gamma[ch + 1] * rsqrtf(var[ch + 1] + BN_EPS);
        float b1 = beta[ch + 1] - mean[ch + 1] * i1;
#pragma unroll
        for (int mt = 0; mt < 2; mt++) {
            int p = p0 + wm * 32 + mt * 16 + grp;
            float* a4 = acc[mt][nt];
            size_t row = (size_t)(ch >> 1) * HW;
            out2[row + p]     = bfpack(fmaxf(a4[0] * i0 + b0, 0.f),
                                       fmaxf(a4[1] * i1 + b1, 0.f));
            out2[row + p + 8] = bfpack(fmaxf(a4[2] * i0 + b0, 0.f),
                                       fmaxf(a4[3] * i1 + b1, 0.f));
        }
    }
}

// ---------------------------------------------------------------------------
// GEMM2: q'/k' -> g_qk2 (pairs along d); v -> g_v2 (pairs along y via shfl).
// grid (8, 12, NB)
// ---------------------------------------------------------------------------
__global__ __launch_bounds__(256, 2) void k_gemm2(
    const float* __restrict__ pos_h, const float* __restrict__ pos_w) {
    extern __shared__ uint32_t smp[];
    int n = blockIdx.z, p0 = blockIdx.x * 128, c0 = blockIdx.y * 128;
    int tid = threadIdx.x, lane = tid & 31, warp = tid >> 5;
    int wm = warp & 3, wh = warp >> 2;
    int grp = lane >> 2, tg = lane & 3;
    float acc[2][8][4] = {};
    gemm_loop(smp, g_out12 + (size_t)n * (MID / 2) * HW + p0,
              g_wqkvu + (size_t)blockIdx.y * (MID * 64), MID / 32,
              acc, wm, wh, lane, tid);
#pragma unroll
    for (int nt = 0; nt < 8; nt++) {
        int ch = c0 + wh * 64 + nt * 8 + 2 * tg;      // even
#pragma unroll
        for (int mt = 0; mt < 2; mt++) {
            int p = p0 + wm * 32 + mt * 16 + grp;
            float* a4 = acc[mt][nt];
            if (c0 < 512) {                          // q' pairs (d, d+1)
                uint32_t* q = g_qk2 + ((size_t)n * 512 + (ch >> 1)) * HW;
                q[p]     = bfpack(a4[0] * ATT_SCALE, a4[1] * ATT_SCALE);
                q[p + 8] = bfpack(a4[2] * ATT_SCALE, a4[3] * ATT_SCALE);
            } else if (c0 < 1024) {                  // k' = k + emb, pairs (d, d+1)
                int d0 = ch & 127, d1 = (ch + 1) & 127;
                uint32_t* q = g_qk2 + ((size_t)n * 512 + (ch >> 1)) * HW;
                int pa = p, pb = p + 8;
                float e00 = pos_h[(pa >> 5) * DQK + d0] + pos_w[(pa & 31) * DQK + d0];
                float e01 = pos_h[(pa >> 5) * DQK + d1] + pos_w[(pa & 31) * DQK + d1];
                float e10 = pos_h[(pb >> 5) * DQK + d0] + pos_w[(pb & 31) * DQK + d0];
                float e11 = pos_h[(pb >> 5) * DQK + d1] + pos_w[(pb & 31) * DQK + d1];
                q[pa] = bfpack(a4[0] + e00, a4[1] + e01);
                q[pb] = bfpack(a4[2] + e10, a4[3] + e11);
            } else {                                 // v -> g_v2 pairs along y
                int d = ch - 1024;                   // even
                float s0 = __shfl_xor_sync(0xffffffff, a4[0], 4);
                float s1 = __shfl_xor_sync(0xffffffff, a4[1], 4);
                float s2 = __shfl_xor_sync(0xffffffff, a4[2], 4);
                float s3 = __shfl_xor_sync(0xffffffff, a4[3], 4);
                if ((grp & 1) == 0) {                // p even: owns pairs (p,p+1),(p+8,p+9)
                    size_t y2a = (size_t)n * 512 + (p >> 1);
                    size_t y2b = (size_t)n * 512 + ((p + 8) >> 1);
                    *(uint2*)(g_v2 + y2a * 512 + d) =
                        make_uint2(bfpack(a4[0], s0), bfpack(a4[1], s1));
                    *(uint2*)(g_v2 + y2b * 512 + d) =
                        make_uint2(bfpack(a4[2], s2), bfpack(a4[3], s3));
                }
            }
        }
    }
}

// ---------------------------------------------------------------------------
// Flash attention FA2-style: x-tile 64, 128 threads, 4 warps x (16 pos, 128 y),
// register-resident softmax + P, 3-buffer cp.async K/V ring.
// ---------------------------------------------------------------------------
__global__ __launch_bounds__(128) void k_flash() {
    __shared__ uint32_t smu[64 * QLD + 3 * CH_SZ];   // 8832 u32 = 34.5 KB
    uint32_t* Qs   = smu;                            // [64 x][QLD d2]
    uint32_t* ring = smu + 64 * QLD;                 // 3 x [16][CLD]
    uint32_t* Ob   = smu;                            // reused: [64 x][OLD d2]

    int z = blockIdx.z, n = z >> 2, head = z & 3;
    int x0 = blockIdx.x * 64;
    int tid = threadIdx.x, lane = tid & 31, warp = tid >> 5;
    int grp = lane >> 2, tg = lane & 3;
    int r0 = warp * 16 + grp;                        // warp-owned rows r0, r0+8

    const uint32_t* qp2 = g_qk2 + ((size_t)n * 512 + head * 64) * HW;   // [64 d2][1024 x]
    const uint32_t* kp2 = qp2 + (size_t)256 * HW;                       // [64 d2][1024 y]
    const uint32_t* v2p = g_v2 + (size_t)n * 512 * 512 + head * 128;    // [512 y2][512], slice

    auto load_chunk = [&](int t) {
        uint32_t* buf = ring + (t % 3) * CH_SZ;
        int j = t >> 3, ph = t & 7;
        const uint32_t* src;
        size_t ld;
        if (ph < 4) { src = kp2 + (size_t)(ph * 16) * HW + j * 128; ld = HW; }
        else        { src = v2p + (size_t)(j * 64 + (ph - 4) * 16) * 512; ld = 512; }
#pragma unroll
        for (int i = 0; i < 4; i++) {
            int g = tid + i * 128, k = g >> 5, cq = (g & 31) * 4;
            cp16u(buf + k * CLD + cq, src + (size_t)k * ld + cq);
        }
        CP_COMMIT;
    };

    load_chunk(0);
    load_chunk(1);

    // Q tile [64 x][64 d2], transposed from [d2][x]
#pragma unroll
    for (int i = 0; i < 8; i++) {
        int g = tid + i * 128;                // 1024 uint4
        int d2 = g >> 4, xq = (g & 15) * 4;
        uint4 v = *(const uint4*)(qp2 + (size_t)d2 * HW + x0 + xq);
        Qs[(xq + 0) * QLD + d2] = v.x;
        Qs[(xq + 1) * QLD + d2] = v.y;
        Qs[(xq + 2) * QLD + d2] = v.z;
        Qs[(xq + 3) * QLD + d2] = v.w;
    }
    float m0 = -1e30f, m1 = -1e30f, l0 = 0.f, l1 = 0.f;
    float acc_s[16][4] = {};
    float acc_o[16][4] = {};
    __syncthreads();

    for (int j = 0; j < 8; j++) {
        // ---- S = Q @ K'^T : 4 chunks of d32 ----
        for (int c = 0; c < 4; c++) {
            int t = j * 8 + c;
            if (t == 63) { CP_WAIT0; } else { CP_WAIT1; }
            __syncthreads();
            if (t + 2 < 64) load_chunk(t + 2);
            const uint32_t* B = ring + (t % 3) * CH_SZ;
#pragma unroll
            for (int sub = 0; sub < 2; sub++) {
                const uint32_t* ap = Qs + r0 * QLD + c * 16 + sub * 8 + tg;
                uint32_t a0 = ap[0];
                uint32_t a1 = ap[8 * QLD];
                uint32_t a2 = ap[4];
                uint32_t a3 = ap[8 * QLD + 4];
#pragma unroll
                for (int nt = 0; nt < 16; nt++) {
                    uint32_t b0 = B[(sub * 8 + tg) * CLD + nt * 8 + grp];
                    uint32_t b1 = B[(sub * 8 + 4 + tg) * CLD + nt * 8 + grp];
                    MMA_BF16(acc_s[nt], a0, a1, a2, a3, b0, b1);
                }
            }
        }
        // ---- warp-local online softmax (rows r0, r0+8) ----
        {
            float ml0 = -1e30f, ml1 = -1e30f;
#pragma unroll
            for (int nt = 0; nt < 16; nt++) {
                ml0 = fmaxf(ml0, fmaxf(acc_s[nt][0], acc_s[nt][1]));
                ml1 = fmaxf(ml1, fmaxf(acc_s[nt][2], acc_s[nt][3]));
            }
            ml0 = fmaxf(ml0, __shfl_xor_sync(0xffffffff, ml0, 1));
            ml0 = fmaxf(ml0, __shfl_xor_sync(0xffffffff, ml0, 2));
            ml1 = fmaxf(ml1, __shfl_xor_sync(0xffffffff, ml1, 1));
            ml1 = fmaxf(ml1, __shfl_xor_sync(0xffffffff, ml1, 2));
            float mn0 = fmaxf(m0, ml0), mn1 = fmaxf(m1, ml1);
            float sc0 = __expf(m0 - mn0), sc1 = __expf(m1 - mn1);
            m0 = mn0; m1 = mn1;
            float s0 = 0.f, s1 = 0.f;
#pragma unroll
            for (int nt = 0; nt < 16; nt++) {
                float e0 = __expf(acc_s[nt][0] - mn0);
                float e1 = __expf(acc_s[nt][1] - mn0);
                float e2 = __expf(acc_s[nt][2] - mn1);
                float e3 = __expf(acc_s[nt][3] - mn1);
                acc_s[nt][0] = e0; acc_s[nt][1] = e1;
                acc_s[nt][2] = e2; acc_s[nt][3] = e3;
                s0 += e0 + e1; s1 += e2 + e3;
            }
            s0 += __shfl_xor_sync(0xffffffff, s0, 1);
            s0 += __shfl_xor_sync(0xffffffff, s0, 2);
            s1 += __shfl_xor_sync(0xffffffff, s1, 1);
            s1 += __shfl_xor_sync(0xffffffff, s1, 2);
            l0 = l0 * sc0 + s0;
            l1 = l1 * sc1 + s1;
#pragma unroll
            for (int nt = 0; nt < 16; nt++) {
                acc_o[nt][0] *= sc0; acc_o[nt][1] *= sc0;
                acc_o[nt][2] *= sc1; acc_o[nt][3] *= sc1;
            }
        }
        // ---- O += P @ V : 4 chunks of y32, P packed from registers ----
        for (int c = 0; c < 4; c++) {
            int t = j * 8 + 4 + c;
            if (t == 63) { CP_WAIT0; } else { CP_WAIT1; }
            __syncthreads();
            if (t + 2 < 64) load_chunk(t + 2);
            const uint32_t* B = ring + (t % 3) * CH_SZ;
#pragma unroll
            for (int sub = 0; sub < 2; sub++) {
                int qp = c * 2 + sub;                // 16-y group index 0..7
                uint32_t a0 = bfpack(acc_s[2 * qp][0],     acc_s[2 * qp][1]);
                uint32_t a1 = bfpack(acc_s[2 * qp][2],     acc_s[2 * qp][3]);
                uint32_t a2 = bfpack(acc_s[2 * qp + 1][0], acc_s[2 * qp + 1][1]);
                uint32_t a3 = bfpack(acc_s[2 * qp + 1][2], acc_s[2 * qp + 1][3]);
#pragma unroll
                for (int nt = 0; nt < 16; nt++) {
                    uint32_t b0 = B[(sub * 8 + tg) * CLD + nt * 8 + grp];
                    uint32_t b1 = B[(sub * 8 + 4 + tg) * CLD + nt * 8 + grp];
                    MMA_BF16(acc_o[nt], a0, a1, a2, a3, b0, b1);
                }
            }
        }
    }

    // ---- epilogue: O /= l, relu, pack along d, smem transpose, store ----
    float inv0 = 1.f / l0, inv1 = 1.f / l1;
    __syncthreads();                                 // done with Qs/ring
#pragma unroll
    for (int nt = 0; nt < 16; nt++) {
        int d2 = nt * 4 + tg;
        Ob[r0 * OLD + d2] = bfpack(fmaxf(acc_o[nt][0] * inv0, 0.f),
                                   fmaxf(acc_o[nt][1] * inv0, 0.f));
        Ob[(r0 + 8) * OLD + d2] = bfpack(fmaxf(acc_o[nt][2] * inv1, 0.f),
                                         fmaxf(acc_o[nt][3] * inv1, 0.f));
    }
    __syncthreads();
    uint32_t* op2 = g_attn2 + ((size_t)n * (MID / 2) + head * (DQK / 2)) * HW;
#pragma unroll
    for (int i = 0; i < 32; i++) {
        int g = tid + i * 128;               // 4096 = 64 d2 * 64 x
        int d2 = g >> 6, xo = g & 63;
        op2[(size_t)d2 * HW + x0 + xo] = Ob[xo * OLD + d2];
    }
}

// ---------------------------------------------------------------------------
// GEMM3: out[ch][pos] = relu(BN(attn^T @ w3^T) + x)   grid (8, 16, NB)
// ---------------------------------------------------------------------------
__global__ __launch_bounds__(256, 2) void k_gemm3(
    const float* __restrict__ gamma, const float* __restrict__ beta,
    const float* __restrict__ mean, const float* __restrict__ var,
    const float* __restrict__ x, float* __restrict__ out) {
    extern __shared__ uint32_t smp[];
    int n = blockIdx.z, p0 = blockIdx.x * 128, c0 = blockIdx.y * 128;
    int tid = threadIdx.x, lane = tid & 31, warp = tid >> 5;
    int wm = warp & 3, wh = warp >> 2;
    int grp = lane >> 2, tg = lane & 3;
    float acc[2][8][4] = {};
    gemm_loop(smp, g_attn2 + (size_t)n * (MID / 2) * HW + p0,
              g_w3u + (size_t)blockIdx.y * (MID * 64), MID / 32,
              acc, wm, wh, lane, tid);
#pragma unroll
    for (int nt = 0; nt < 8; nt++) {
        int ch = c0 + wh * 64 + nt * 8 + 2 * tg;
        float i0 = gamma[ch] * rsqrtf(var[ch] + BN_EPS);
        float b0 = beta[ch] - mean[ch] * i0;
        float i1 = gamma[ch + 1] * rsqrtf(var[ch + 1] + BN_EPS);
        float b1 = beta[ch + 1] - mean[ch + 1] * i1;
#pragma unroll
        for (int mt = 0; mt < 2; mt++) {
            int p = p0 + wm * 32 + mt * 16 + grp;
            float* a4 = acc[mt][nt];
            size_t e0 = (size_t)n * CIN * HW + (size_t)ch * HW + p;
            size_t e1 = e0 + HW;
            out[e0]     = fmaxf(a4[0] * i0 + b0 + x[e0], 0.f);
            out[e1]     = fmaxf(a4[1] * i1 + b1 + x[e1], 0.f);
            out[e0 + 8] = fmaxf(a4[2] * i0 + b0 + x[e0 + 8], 0.f);
            out[e1 + 8] = fmaxf(a4[3] * i1 + b1 + x[e1 + 8], 0.f);
        }
    }
}

// ---------------------------------------------------------------------------
extern "C" void kernel_launch(void* const* d_in, const int* in_sizes, int n_in,
                              void* d_out, int out_size) {
    const float* x       = (const float*)d_in[0];
    const float* conv1_w = (const float*)d_in[1];
    const float* gamma1  = (const float*)d_in[2];
    const float* beta1   = (const float*)d_in[3];
    const float* mean1   = (const float*)d_in[4];
    const float* var1    = (const float*)d_in[5];
    const float* qk_w    = (const float*)d_in[6];
    const float* v_w     = (const float*)d_in[7];
    const float* pos_h   = (const float*)d_in[8];
    const float* pos_w   = (const float*)d_in[9];
    const float* conv3_w = (const float*)d_in[10];
    const float* gamma3  = (const float*)d_in[11];
    const float* beta3   = (const float*)d_in[12];
    const float* mean3   = (const float*)d_in[13];
    const float* var3    = (const float*)d_in[14];
    float* out = (float*)d_out;

    cudaFuncSetAttribute(k_gemm1, cudaFuncAttributeMaxDynamicSharedMemorySize,
                         GEMM_SMEM);
    cudaFuncSetAttribute(k_gemm2, cudaFuncAttributeMaxDynamicSharedMemorySize,
                         GEMM_SMEM);
    cudaFuncSetAttribute(k_gemm3, cudaFuncAttributeMaxDynamicSharedMemorySize,
                         GEMM_SMEM);

    uint32_t *p_x2, *p_w1, *p_wqkv, *p_w3;
    cudaGetSymbolAddress((void**)&p_x2, g_x2);
    cudaGetSymbolAddress((void**)&p_w1, g_w1u);
    cudaGetSymbolAddress((void**)&p_wqkv, g_wqkvu);
    cudaGetSymbolAddress((void**)&p_w3, g_w3u);

    dim3 blk256(256);
    {
        size_t nt = (size_t)NB * (CIN / 2) * HW;
        k_roundx<<<(unsigned)(nt / 256), blk256>>>(x, p_x2);
    }
    k_repackb<<<(MID * CIN / 2 + 255) / 256, blk256>>>(conv1_w, p_w1, MID, CIN);
    k_repackb<<<(1024 * MID / 2 + 255) / 256, blk256>>>(qk_w, p_wqkv, 1024, MID);
    k_repackb<<<(512 * MID / 2 + 255) / 256, blk256>>>(v_w,
                                                       p_wqkv + (size_t)1024 * MID / 2,
                                                       512, MID);
    k_repackb<<<(CIN * MID / 2 + 255) / 256, blk256>>>(conv3_w, p_w3, CIN, MID);

    k_gemm1<<<dim3(8, 4, NB), blk256, GEMM_SMEM>>>(gamma1, beta1, mean1, var1);
    k_gemm2<<<dim3(8, 12, NB), blk256, GEMM_SMEM>>>(pos_h, pos_w);
    k_flash<<<dim3(16, 1, NB * NHEAD), dim3(128)>>>();
    k_gemm3<<<dim3(8, 16, NB), blk256, GEMM_SMEM>>>(gamma3, beta3, mean3, var3, x, out);
}